// round 10
// baseline (speedup 1.0000x reference)
#include <cuda_runtime.h>
#include <cuda_bf16.h>
#include <math.h>

// Problem constants
#define B   4
#define C   64
#define H   128
#define W   128
#define G   8
#define CPG 8
#define NPT 9
#define PIX (H*W)

typedef unsigned long long u64;
typedef unsigned int u32;

// ---------------------------------------------------------------------------
// Static device scratch
// ---------------------------------------------------------------------------
__device__ __align__(16) float g_xt[B*G*PIX*CPG];         // anchor (b,g,pix,c)
__device__ __align__(16) float g_off[B*G*PIX*28];         // offsets+masks
__device__ __align__(16) float g_tgt[B*PIX*64];           // deform out NHWC fp32
__device__ __align__(16) __nv_bfloat16 g_cath[B*PIX*128]; // cat(target,anchor) hi
__device__ __align__(16) __nv_bfloat16 g_catl[B*PIX*128]; // lo
__device__ __align__(16) __nv_bfloat16 g_midh[B*PIX*64];  // conv1 out hi
__device__ __align__(16) __nv_bfloat16 g_midl[B*PIX*64];  // lo
__device__ __align__(16) __nv_bfloat16 g_w1h[64*9*128];   // w1 [oc][tap][cin]
__device__ __align__(16) __nv_bfloat16 g_w1l[64*9*128];
__device__ __align__(16) __nv_bfloat16 g_w2h[64*9*64];
__device__ __align__(16) __nv_bfloat16 g_w2l[64*9*64];

// ---------------------------------------------------------------------------
// PTX helpers (sm_80-class only — compute_103-safe)
// ---------------------------------------------------------------------------
__device__ __forceinline__ u32 smem_u32(const void* p) {
    u32 a;
    asm("{ .reg .u64 t; cvta.to.shared.u64 t, %1; cvt.u32.u64 %0, t; }" : "=r"(a) : "l"(p));
    return a;
}
__device__ __forceinline__ void cpa16(u32 dst, const void* src, u32 sz) {
    asm volatile("cp.async.cg.shared.global [%0], [%1], 16, %2;"
                 :: "r"(dst), "l"(src), "r"(sz));
}
__device__ __forceinline__ void cp_commit() { asm volatile("cp.async.commit_group;"); }
__device__ __forceinline__ void cp_wait1()  { asm volatile("cp.async.wait_group 1;" ::: "memory"); }
__device__ __forceinline__ void cp_wait0()  { asm volatile("cp.async.wait_group 0;" ::: "memory"); }

__device__ __forceinline__ void ldm4(u32* r, u32 a) {
    asm volatile("ldmatrix.sync.aligned.m8n8.x4.shared.b16 {%0,%1,%2,%3}, [%4];"
                 : "=r"(r[0]), "=r"(r[1]), "=r"(r[2]), "=r"(r[3]) : "r"(a));
}
__device__ __forceinline__ void mma16816(float* d, const u32* a, u32 b0, u32 b1) {
    asm volatile(
        "mma.sync.aligned.m16n8k16.row.col.f32.bf16.bf16.f32 "
        "{%0,%1,%2,%3}, {%4,%5,%6,%7}, {%8,%9}, {%0,%1,%2,%3};"
        : "+f"(d[0]), "+f"(d[1]), "+f"(d[2]), "+f"(d[3])
        : "r"(a[0]), "r"(a[1]), "r"(a[2]), "r"(a[3]), "r"(b0), "r"(b1));
}
__device__ __forceinline__ u32 pack_bf16(float a, float b) {
    __nv_bfloat16 ha = __float2bfloat16(a), hb = __float2bfloat16(b);
    return (u32)__bfloat16_as_ushort(ha) | ((u32)__bfloat16_as_ushort(hb) << 16);
}

// ---------------------------------------------------------------------------
// Kernel 1: fused offset-conv (18ch) + mask-conv (9ch) + sigmoid, per group.
// ---------------------------------------------------------------------------
__global__ __launch_bounds__(256)
void offset_mask_conv(const float* __restrict__ o,
                      const float* __restrict__ pw, const float* __restrict__ pb,
                      const float* __restrict__ mw, const float* __restrict__ mb)
{
    __shared__ float tsm[CPG * 18 * 18];
    __shared__ float wsm[72 * 27];
    __shared__ float bsm[27];

    const int tx = threadIdx.x, ty = threadIdx.y;
    const int tid = ty * 16 + tx;
    const int bg = blockIdx.z;
    const int b = bg >> 3, g = bg & 7;
    const int row0 = blockIdx.y * 16, col0 = blockIdx.x * 16;

    for (int idx = tid; idx < 72 * 27; idx += 256) {
        int ck = idx / 27, oc = idx % 27;
        int c = ck / 9, k = ck % 9;
        float v;
        if (oc < 18) v = pw[((g * 18 + oc) * CPG + c) * 9 + k];
        else         v = mw[((g * 9 + (oc - 18)) * CPG + c) * 9 + k];
        wsm[idx] = v;
    }
    if (tid < 27) bsm[tid] = (tid < 18) ? pb[g * 18 + tid] : mb[g * 9 + (tid - 18)];

    const float* src = o + ((size_t)(b * C + g * CPG)) * PIX;
    for (int idx = tid; idx < CPG * 324; idx += 256) {
        int c = idx / 324, rem = idx % 324;
        int rr = rem / 18, cc = rem % 18;
        int gy = row0 + rr - 1, gx = col0 + cc - 1;
        float v = 0.f;
        if (gy >= 0 && gy < H && gx >= 0 && gx < W)
            v = src[c * PIX + gy * W + gx];
        tsm[idx] = v;
    }
    __syncthreads();

    float acc[27];
#pragma unroll
    for (int oc = 0; oc < 27; ++oc) acc[oc] = bsm[oc];

#pragma unroll
    for (int c = 0; c < CPG; ++c) {
#pragma unroll
        for (int ky = 0; ky < 3; ++ky) {
#pragma unroll
            for (int kx = 0; kx < 3; ++kx) {
                float xv = tsm[c * 324 + (ty + ky) * 18 + (tx + kx)];
                const float* wr = wsm + (c * 9 + ky * 3 + kx) * 27;
#pragma unroll
                for (int oc = 0; oc < 27; ++oc)
                    acc[oc] = fmaf(xv, wr[oc], acc[oc]);
            }
        }
    }

    const int y = row0 + ty, x = col0 + tx;
    float* op = g_off + ((size_t)bg * PIX + y * W + x) * 28;
#pragma unroll
    for (int oc = 0; oc < 18; ++oc) op[oc] = acc[oc];
#pragma unroll
    for (int oc = 18; oc < 27; ++oc) op[oc] = 1.f / (1.f + expf(-acc[oc]));
}

// ---------------------------------------------------------------------------
// Kernel 2: anchor -> g_xt + cat NHWC bf16 split (channels 64..127)
// ---------------------------------------------------------------------------
__global__ __launch_bounds__(256)
void transpose_anchor(const float* __restrict__ anchor)
{
    int t = blockIdx.x * 256 + threadIdx.x;
    if (t >= B * G * PIX) return;
    int pix = t & (PIX - 1);
    int bg = t >> 14;
    int b = bg >> 3, g = bg & 7;
    const float* src = anchor + ((size_t)(b * C + g * CPG)) * PIX + pix;
    float v[8];
#pragma unroll
    for (int c = 0; c < CPG; ++c) v[c] = src[c * PIX];
#pragma unroll
    for (int c = 0; c < CPG; ++c) g_xt[(size_t)t * CPG + c] = v[c];

    size_t pixg = (size_t)b * PIX + pix;
    u32 hw[4], lw[4];
#pragma unroll
    for (int q = 0; q < 4; ++q) {
        float v0 = v[2*q], v1 = v[2*q+1];
        hw[q] = pack_bf16(v0, v1);
        float h0 = __bfloat162float(__ushort_as_bfloat16((unsigned short)(hw[q] & 0xFFFF)));
        float h1 = __bfloat162float(__ushort_as_bfloat16((unsigned short)(hw[q] >> 16)));
        lw[q] = pack_bf16(v0 - h0, v1 - h1);
    }
    *(uint4*)(g_cath + pixg * 128 + 64 + g * 8) = make_uint4(hw[0], hw[1], hw[2], hw[3]);
    *(uint4*)(g_catl + pixg * 128 + 64 + g * 8) = make_uint4(lw[0], lw[1], lw[2], lw[3]);
}

// ---------------------------------------------------------------------------
// Kernel 2b: weight prep — [oc][cin][k] -> [oc][k][cin], bf16 hi/lo split
// ---------------------------------------------------------------------------
__global__ __launch_bounds__(256)
void prep_weights(const float* __restrict__ w1, const float* __restrict__ w2)
{
    int t = blockIdx.x * 256 + threadIdx.x;
    if (t < 64 * 9 * 128) {
        int oc = t / (9 * 128), rem = t % (9 * 128);
        int s = rem / 128, c = rem % 128;
        float v = w1[(oc * 128 + c) * 9 + s];
        __nv_bfloat16 h = __float2bfloat16(v);
        g_w1h[(oc * 9 + s) * 128 + c] = h;
        g_w1l[(oc * 9 + s) * 128 + c] = __float2bfloat16(v - __bfloat162float(h));
    }
    if (t < 64 * 9 * 64) {
        int oc = t / (9 * 64), rem = t % (9 * 64);
        int s = rem / 64, c = rem % 64;
        float v = w2[(oc * 64 + c) * 9 + s];
        __nv_bfloat16 h = __float2bfloat16(v);
        g_w2h[(oc * 9 + s) * 64 + c] = h;
        g_w2l[(oc * 9 + s) * 64 + c] = __float2bfloat16(v - __bfloat162float(h));
    }
}

// ---------------------------------------------------------------------------
// Kernel 3: deformable bilinear sampling + modulation + group 3x3 "conv"
// ---------------------------------------------------------------------------
__global__ __launch_bounds__(256)
void deform_kernel(const float* __restrict__ cw)
{
    __shared__ float cw_s[NPT * CPG * CPG];

    const int tid = threadIdx.x;
    const int bg = blockIdx.y;
    const int b = bg >> 3, g = bg & 7;

    for (int idx = tid; idx < NPT * 64; idx += 256) {
        int n = idx / 64, rem = idx % 64;
        int c = rem / 8, oc = rem % 8;
        cw_s[idx] = cw[(((g * CPG + oc) * CPG + c) * NPT) + n];
    }
    __syncthreads();

    const int pixel = blockIdx.x * 256 + tid;
    const int i = pixel >> 7, j = pixel & (W - 1);

    float offv[28];
    const float4* op4 = (const float4*)(g_off + ((size_t)bg * PIX + pixel) * 28);
#pragma unroll
    for (int q = 0; q < 7; ++q) *(((float4*)offv) + q) = op4[q];

    const float4* xt4 = (const float4*)(g_xt + (size_t)bg * PIX * CPG);

    float acc[8];
#pragma unroll
    for (int oc = 0; oc < 8; ++oc) acc[oc] = 0.f;

#pragma unroll
    for (int n = 0; n < NPT; ++n) {
        const int pnx = n / 3 - 1, pny = n % 3 - 1;
        float px = (float)(i + 1 + pnx) + offv[n];
        float py = (float)(j + 1 + pny) + offv[NPT + n];
        float m  = offv[18 + n];

        float fx = floorf(px), fy = floorf(py);
        float qxl = fminf(fmaxf(fx,       0.f), (float)(H - 1));
        float qxr = fminf(fmaxf(fx + 1.f, 0.f), (float)(H - 1));
        float qyl = fminf(fmaxf(fy,       0.f), (float)(W - 1));
        float qyr = fminf(fmaxf(fy + 1.f, 0.f), (float)(W - 1));
        float pxc = fminf(fmaxf(px, 0.f), (float)(H - 1));
        float pyc = fminf(fmaxf(py, 0.f), (float)(W - 1));

        float glt = (1.f + (qxl - pxc)) * (1.f + (qyl - pyc));
        float grb = (1.f - (qxr - pxc)) * (1.f - (qyr - pyc));
        float glb = (1.f + (qxl - pxc)) * (1.f - (qyr - pyc));
        float grt = (1.f - (qxr - pxc)) * (1.f + (qyl - pyc));

        int ixl = (int)qxl, ixr = (int)qxr, iyl = (int)qyl, iyr = (int)qyr;

        const float4* pa  = xt4 + (((ixl << 7) + iyl) << 1);
        const float4* pb_ = xt4 + (((ixr << 7) + iyr) << 1);
        const float4* pc  = xt4 + (((ixl << 7) + iyr) << 1);
        const float4* pd  = xt4 + (((ixr << 7) + iyl) << 1);

        float av[8], bv[8], cv[8], dv[8];
        *(float4*)&av[0] = pa[0];  *(float4*)&av[4] = pa[1];
        *(float4*)&bv[0] = pb_[0]; *(float4*)&bv[4] = pb_[1];
        *(float4*)&cv[0] = pc[0];  *(float4*)&cv[4] = pc[1];
        *(float4*)&dv[0] = pd[0];  *(float4*)&dv[4] = pd[1];

        const float* wn = cw_s + n * 64;
#pragma unroll
        for (int c = 0; c < CPG; ++c) {
            float vc = fmaf(glt, av[c], fmaf(grb, bv[c], fmaf(glb, cv[c], grt * dv[c]))) * m;
            const float* wr = wn + c * 8;
#pragma unroll
            for (int oc = 0; oc < 8; ++oc)
                acc[oc] = fmaf(vc, wr[oc], acc[oc]);
        }
    }

    size_t pixg = (size_t)b * PIX + pixel;
    *(float4*)(g_tgt + pixg * 64 + g * 8)     = make_float4(acc[0], acc[1], acc[2], acc[3]);
    *(float4*)(g_tgt + pixg * 64 + g * 8 + 4) = make_float4(acc[4], acc[5], acc[6], acc[7]);

    u32 hw[4], lw[4];
#pragma unroll
    for (int q = 0; q < 4; ++q) {
        float v0 = acc[2*q], v1 = acc[2*q+1];
        hw[q] = pack_bf16(v0, v1);
        float h0 = __bfloat162float(__ushort_as_bfloat16((unsigned short)(hw[q] & 0xFFFF)));
        float h1 = __bfloat162float(__ushort_as_bfloat16((unsigned short)(hw[q] >> 16)));
        lw[q] = pack_bf16(v0 - h0, v1 - h1);
    }
    *(uint4*)(g_cath + pixg * 128 + g * 8) = make_uint4(hw[0], hw[1], hw[2], hw[3]);
    *(uint4*)(g_catl + pixg * 128 + g * 8) = make_uint4(lw[0], lw[1], lw[2], lw[3]);
}

// ---------------------------------------------------------------------------
// Kernels 4/5: mma.sync (HMMA) implicit-GEMM 3x3 conv, split-bf16, fp32 acc.
// CTA = one image row: M=128 px, N=64 oc, 4 warps (M=32 each), 128 threads.
// Stages: cin-block(64) x 9 taps, cp.async double-buffered.
// SMEM per stage buffer: Ah[128][72] Al[128][72] Bh[64][72] Bl[64][72] bf16.
// Row stride 72 bf16 (144B) => conflict-free ldmatrix/cp.async.
// B is [oc][cin] row-major = col-major KxN: fragment needs NON-trans ldmatrix.
// ---------------------------------------------------------------------------
#define ASTRIDE_B 144          // 72 bf16
#define AL_OFF    18432        // bytes
#define BH_OFF    36864
#define BL_OFF    46080
#define BUF_BYTES 55296
#define DSMEM_BYTES (2*BUF_BYTES)

template <int MODE>
__global__ __launch_bounds__(128)
void conv_mma(const float* __restrict__ bias, float* __restrict__ out)
{
    constexpr int CINT = (MODE == 0) ? 128 : 64;
    constexpr int S = (MODE == 0) ? 18 : 9;

    extern __shared__ __align__(128) char dsm[];
    __shared__ float bsm[64];

    const u32 sbase = smem_u32(dsm);
    const int tid = threadIdx.x;
    const int lane = tid & 31;
    const int w = tid >> 5;
    const int y = blockIdx.x;
    const int bb = blockIdx.y;

    const __nv_bfloat16* SRC_H = (MODE == 0) ? g_cath : g_midh;
    const __nv_bfloat16* SRC_L = (MODE == 0) ? g_catl : g_midl;
    const __nv_bfloat16* WT_H  = (MODE == 0) ? g_w1h : g_w2h;
    const __nv_bfloat16* WT_L  = (MODE == 0) ? g_w1l : g_w2l;

    if (tid < 64) bsm[tid] = bias[tid];

    // ---- stage loader ----
    auto issue = [&](int s, int buf) {
        int cb = s / 9, tap = s % 9;
        int sy = tap / 3, sx = tap % 3;
        int gy = y + sy - 1;
        u32 bufoff = (u32)buf * BUF_BYTES;
        // A: px = tid
        {
            int gx = tid + sx - 1;
            bool ok = (gy >= 0 && gy < H && gx >= 0 && gx < W);
            int gyc = min(max(gy, 0), H - 1);
            int gxc = min(max(gx, 0), W - 1);
            size_t gp = ((size_t)bb * PIX + (size_t)gyc * W + gxc) * CINT + cb * 64;
            const __nv_bfloat16* sh = SRC_H + gp;
            const __nv_bfloat16* sl = SRC_L + gp;
            u32 dh = sbase + bufoff + (u32)tid * ASTRIDE_B;
            u32 dl = dh + AL_OFF;
            u32 sz = ok ? 16u : 0u;
#pragma unroll
            for (int i = 0; i < 8; ++i) {
                cpa16(dh + i * 16, sh + i * 8, sz);
                cpa16(dl + i * 16, sl + i * 8, sz);
            }
        }
        // B: 64 oc x 64 cin; thread -> oc = tid/2, half = tid&1 (32 ch)
        {
            int oc = tid >> 1, half = tid & 1;
            size_t wp = ((size_t)oc * 9 + tap) * CINT + cb * 64 + half * 32;
            u32 dh = sbase + bufoff + BH_OFF + (u32)oc * ASTRIDE_B + (u32)half * 64;
            u32 dl = dh + (BL_OFF - BH_OFF);
#pragma unroll
            for (int i = 0; i < 4; ++i) {
                cpa16(dh + i * 16, WT_H + wp + i * 8, 16u);
                cpa16(dl + i * 16, WT_L + wp + i * 8, 16u);
            }
        }
        cp_commit();
    };

    float acc[2][8][4];
#pragma unroll
    for (int mt = 0; mt < 2; ++mt)
#pragma unroll
        for (int nt = 0; nt < 8; ++nt)
#pragma unroll
            for (int c = 0; c < 4; ++c) acc[mt][nt][c] = 0.f;

    const u32 qoff = (u32)(lane & 15) * ASTRIDE_B + (u32)(lane >> 4) * 16;

    issue(0, 0);

    for (int s = 0; s < S; ++s) {
        const int buf = s & 1;
        if (s + 1 < S) { issue(s + 1, buf ^ 1); cp_wait1(); }
        else           { cp_wait0(); }
        __syncthreads();

        const u32 aBase = sbase + (u32)buf * BUF_BYTES;
        const u32 bBase = aBase + BH_OFF;

#pragma unroll
        for (int kk = 0; kk < 4; ++kk) {
            u32 ah[2][4], al[2][4];
#pragma unroll
            for (int mt = 0; mt < 2; ++mt) {
                u32 rowb = (u32)(w * 32 + mt * 16) * ASTRIDE_B + (u32)kk * 32 + qoff;
                ldm4(ah[mt], aBase + rowb);
                ldm4(al[mt], aBase + AL_OFF + rowb);
            }
            u32 bh[4][4], bl[4][4];
#pragma unroll
            for (int nt2 = 0; nt2 < 4; ++nt2) {
                u32 rowb = (u32)(nt2 * 16) * ASTRIDE_B + (u32)kk * 32 + qoff;
                ldm4(bh[nt2], bBase + rowb);                       // NON-trans (fixed)
                ldm4(bl[nt2], bBase + (BL_OFF - BH_OFF) + rowb);   // NON-trans (fixed)
            }
#pragma unroll
            for (int mt = 0; mt < 2; ++mt) {
#pragma unroll
                for (int nt = 0; nt < 8; ++nt) {
                    int nt2 = nt >> 1, odd = nt & 1;
                    u32 b0h = bh[nt2][odd], b1h = bh[nt2][odd + 2];
                    mma16816(acc[mt][nt], ah[mt], b0h, b1h);   // wh * xh
                    mma16816(acc[mt][nt], al[mt], b0h, b1h);   // wh * xl
                    u32 b0l = bl[nt2][odd], b1l = bl[nt2][odd + 2];
                    mma16816(acc[mt][nt], ah[mt], b0l, b1l);   // wl * xh
                }
            }
        }
        __syncthreads();
    }

    // ---- epilogue ----
    const int r0 = lane >> 2;
    const int cp2 = (lane & 3) * 2;

#pragma unroll
    for (int mt = 0; mt < 2; ++mt) {
#pragma unroll
        for (int hh = 0; hh < 2; ++hh) {
            int px = w * 32 + mt * 16 + r0 + hh * 8;
            size_t pixoff = (size_t)y * W + px;
            if (MODE == 0) {
                size_t pg = ((size_t)bb * PIX + pixoff) * 64;
#pragma unroll
                for (int nt = 0; nt < 8; ++nt) {
                    int col = nt * 8 + cp2;
                    float v0 = acc[mt][nt][hh * 2]     + bsm[col];
                    float v1 = acc[mt][nt][hh * 2 + 1] + bsm[col + 1];
                    u32 hw = pack_bf16(v0, v1);
                    float h0 = __bfloat162float(__ushort_as_bfloat16((unsigned short)(hw & 0xFFFF)));
                    float h1 = __bfloat162float(__ushort_as_bfloat16((unsigned short)(hw >> 16)));
                    u32 lw = pack_bf16(v0 - h0, v1 - h1);
                    *(u32*)(g_midh + pg + col) = hw;
                    *(u32*)(g_midl + pg + col) = lw;
                }
            } else {
                const float* tg = g_tgt + ((size_t)bb * PIX + pixoff) * 64;
#pragma unroll
                for (int nt = 0; nt < 8; ++nt) {
                    int col = nt * 8 + cp2;
                    float v0 = acc[mt][nt][hh * 2]     + bsm[col]     + tg[col];
                    float v1 = acc[mt][nt][hh * 2 + 1] + bsm[col + 1] + tg[col + 1];
                    out[((size_t)(bb * 64 + col)) * PIX + pixoff] = v0;
                    out[((size_t)(bb * 64 + col + 1)) * PIX + pixoff] = v1;
                }
            }
        }
    }
}

// ---------------------------------------------------------------------------
extern "C" void kernel_launch(void* const* d_in, const int* in_sizes, int n_in,
                              void* d_out, int out_size)
{
    const float* o      = (const float*)d_in[0];
    const float* anchor = (const float*)d_in[1];
    const float* pw     = (const float*)d_in[2];
    const float* pb     = (const float*)d_in[3];
    const float* mw     = (const float*)d_in[4];
    const float* mb     = (const float*)d_in[5];
    const float* cw     = (const float*)d_in[6];
    const float* w1     = (const float*)d_in[7];
    const float* b1     = (const float*)d_in[8];
    const float* w2     = (const float*)d_in[9];
    const float* b2     = (const float*)d_in[10];
    float* out = (float*)d_out;

    static int smem_set = 0;
    if (!smem_set) {
        cudaFuncSetAttribute(conv_mma<0>, cudaFuncAttributeMaxDynamicSharedMemorySize, DSMEM_BYTES);
        cudaFuncSetAttribute(conv_mma<1>, cudaFuncAttributeMaxDynamicSharedMemorySize, DSMEM_BYTES);
        smem_set = 1;
    }

    offset_mask_conv<<<dim3(W / 16, H / 16, B * G), dim3(16, 16)>>>(o, pw, pb, mw, mb);
    transpose_anchor<<<(B * G * PIX + 255) / 256, 256>>>(anchor);
    prep_weights<<<(64 * 9 * 128 + 255) / 256, 256>>>(w1, w2);
    deform_kernel<<<dim3(PIX / 256, B * G), 256>>>(cw);

    conv_mma<0><<<dim3(H, B), 128, DSMEM_BYTES>>>(b1, nullptr);
    conv_mma<1><<<dim3(H, B), 128, DSMEM_BYTES>>>(b2, out);
}

// round 12
// speedup vs baseline: 1.0468x; 1.0468x over previous
#include <cuda_runtime.h>
#include <cuda_bf16.h>
#include <math.h>

// Problem constants
#define B   4
#define C   64
#define H   128
#define W   128
#define G   8
#define CPG 8
#define NPT 9
#define PIX (H*W)

typedef unsigned long long u64;
typedef unsigned int u32;

// ---------------------------------------------------------------------------
// Static device scratch
// ---------------------------------------------------------------------------
__device__ __align__(16) float g_xt[B*G*PIX*CPG];         // anchor (b,g,pix,c)
__device__ __align__(16) float g_off[B*G*28*PIX];         // SoA: [bg][28][pix]
__device__ __align__(16) float g_tgt[B*PIX*64];           // deform out NHWC fp32
__device__ __align__(16) __nv_bfloat16 g_cath[B*PIX*128]; // cat(target,anchor) hi
__device__ __align__(16) __nv_bfloat16 g_catl[B*PIX*128]; // lo
__device__ __align__(16) __nv_bfloat16 g_midh[B*PIX*64];  // conv1 out hi
__device__ __align__(16) __nv_bfloat16 g_midl[B*PIX*64];  // lo
__device__ __align__(16) __nv_bfloat16 g_w1h[64*9*128];   // w1 [oc][tap][cin]
__device__ __align__(16) __nv_bfloat16 g_w1l[64*9*128];
__device__ __align__(16) __nv_bfloat16 g_w2h[64*9*64];
__device__ __align__(16) __nv_bfloat16 g_w2l[64*9*64];

// ---------------------------------------------------------------------------
// PTX helpers (sm_80-class only — compute_103-safe)
// ---------------------------------------------------------------------------
__device__ __forceinline__ u32 smem_u32(const void* p) {
    u32 a;
    asm("{ .reg .u64 t; cvta.to.shared.u64 t, %1; cvt.u32.u64 %0, t; }" : "=r"(a) : "l"(p));
    return a;
}
__device__ __forceinline__ void cpa16(u32 dst, const void* src, u32 sz) {
    asm volatile("cp.async.cg.shared.global [%0], [%1], 16, %2;"
                 :: "r"(dst), "l"(src), "r"(sz));
}
__device__ __forceinline__ void cp_commit() { asm volatile("cp.async.commit_group;"); }
__device__ __forceinline__ void cp_wait1()  { asm volatile("cp.async.wait_group 1;" ::: "memory"); }
__device__ __forceinline__ void cp_wait0()  { asm volatile("cp.async.wait_group 0;" ::: "memory"); }

__device__ __forceinline__ void ldm4(u32* r, u32 a) {
    asm volatile("ldmatrix.sync.aligned.m8n8.x4.shared.b16 {%0,%1,%2,%3}, [%4];"
                 : "=r"(r[0]), "=r"(r[1]), "=r"(r[2]), "=r"(r[3]) : "r"(a));
}
__device__ __forceinline__ void mma16816(float* d, const u32* a, u32 b0, u32 b1) {
    asm volatile(
        "mma.sync.aligned.m16n8k16.row.col.f32.bf16.bf16.f32 "
        "{%0,%1,%2,%3}, {%4,%5,%6,%7}, {%8,%9}, {%0,%1,%2,%3};"
        : "+f"(d[0]), "+f"(d[1]), "+f"(d[2]), "+f"(d[3])
        : "r"(a[0]), "r"(a[1]), "r"(a[2]), "r"(a[3]), "r"(b0), "r"(b1));
}
__device__ __forceinline__ u32 pack_bf16(float a, float b) {
    __nv_bfloat16 ha = __float2bfloat16(a), hb = __float2bfloat16(b);
    return (u32)__bfloat16_as_ushort(ha) | ((u32)__bfloat16_as_ushort(hb) << 16);
}
#define FMA2(acc, a, b) asm("fma.rn.f32x2 %0, %1, %2, %0;" : "+l"(acc) : "l"(a), "l"(b))
#define PACK_DUP(out, x) asm("mov.b64 %0, {%1, %1};" : "=l"(out) : "r"(__float_as_uint(x)))
#define UNPACK2(lo, hi, v) asm("mov.b64 {%0, %1}, %2;" : "=r"(lo), "=r"(hi) : "l"(v))

// ---------------------------------------------------------------------------
// Kernel 1: fused offset-conv (18ch) + mask-conv (9ch) + sigmoid, FFMA2 accs,
// SoA output. grid (8, 8, B*G), block 256.
// ---------------------------------------------------------------------------
__global__ __launch_bounds__(256)
void offset_mask_conv(const float* __restrict__ o,
                      const float* __restrict__ pw, const float* __restrict__ pb,
                      const float* __restrict__ mw, const float* __restrict__ mb)
{
    __shared__ __align__(16) float tsm[CPG * 18 * 18];
    __shared__ __align__(16) float wsm[72 * 28];   // padded stride 28
    __shared__ __align__(16) float bsm[28];

    const int tid = threadIdx.x;
    const int tx = tid & 15, ty = tid >> 4;
    const int bg = blockIdx.z;
    const int b = bg >> 3, g = bg & 7;
    const int row0 = blockIdx.y * 16, col0 = blockIdx.x * 16;

    for (int idx = tid; idx < 72 * 28; idx += 256) {
        int ck = idx / 28, oc = idx % 28;
        int c = ck / 9, k = ck % 9;
        float v = 0.f;
        if (oc < 18)      v = pw[((g * 18 + oc) * CPG + c) * 9 + k];
        else if (oc < 27) v = mw[((g * 9 + (oc - 18)) * CPG + c) * 9 + k];
        wsm[idx] = v;
    }
    if (tid < 28) bsm[tid] = (tid < 18) ? pb[g * 18 + tid]
                           : (tid < 27) ? mb[g * 9 + (tid - 18)] : 0.f;

    const float* src = o + ((size_t)(b * C + g * CPG)) * PIX;
    for (int idx = tid; idx < CPG * 324; idx += 256) {
        int c = idx / 324, rem = idx % 324;
        int rr = rem / 18, cc = rem % 18;
        int gy = row0 + rr - 1, gx = col0 + cc - 1;
        float v = 0.f;
        if (gy >= 0 && gy < H && gx >= 0 && gx < W)
            v = src[c * PIX + gy * W + gx];
        tsm[idx] = v;
    }
    __syncthreads();

    u64 acc2[14];
    {
        const u64* bp = (const u64*)bsm;
#pragma unroll
        for (int q = 0; q < 14; ++q) acc2[q] = bp[q];
    }

#pragma unroll
    for (int c = 0; c < CPG; ++c) {
#pragma unroll
        for (int ky = 0; ky < 3; ++ky) {
#pragma unroll
            for (int kx = 0; kx < 3; ++kx) {
                float xv = tsm[c * 324 + (ty + ky) * 18 + (tx + kx)];
                u64 xb; PACK_DUP(xb, xv);
                const u64* wr = (const u64*)(wsm + (c * 9 + ky * 3 + kx) * 28);
#pragma unroll
                for (int q = 0; q < 14; ++q)
                    FMA2(acc2[q], wr[q], xb);
            }
        }
    }

    float acc[28];
#pragma unroll
    for (int q = 0; q < 14; ++q) {
        u32 lo, hi;
        UNPACK2(lo, hi, acc2[q]);
        acc[2*q] = __uint_as_float(lo);
        acc[2*q+1] = __uint_as_float(hi);
    }

    const int y = row0 + ty, x = col0 + tx;
    float* op = g_off + (size_t)bg * 28 * PIX + y * W + x;   // SoA: stride PIX
#pragma unroll
    for (int oc = 0; oc < 18; ++oc) op[oc * PIX] = acc[oc];
#pragma unroll
    for (int oc = 18; oc < 27; ++oc) op[oc * PIX] = 1.f / (1.f + expf(-acc[oc]));
}

// ---------------------------------------------------------------------------
// Kernel 2: anchor transpose + cat split, AND weight transpose + split.
// Pure copy work, no smem/syncs. grid covers max(524288, 73728) threads.
// ---------------------------------------------------------------------------
__global__ __launch_bounds__(256)
void prep_data(const float* __restrict__ anchor,
               const float* __restrict__ w1, const float* __restrict__ w2)
{
    int t = blockIdx.x * 256 + threadIdx.x;
    if (t < B * G * PIX) {
        int pix = t & (PIX - 1);
        int bg = t >> 14;
        int b = bg >> 3, g = bg & 7;
        const float* src = anchor + ((size_t)(b * C + g * CPG)) * PIX + pix;
        float v[8];
#pragma unroll
        for (int c = 0; c < CPG; ++c) v[c] = src[c * PIX];
#pragma unroll
        for (int c = 0; c < CPG; ++c) g_xt[(size_t)t * CPG + c] = v[c];

        size_t pixg = (size_t)b * PIX + pix;
        u32 hw[4], lw[4];
#pragma unroll
        for (int q = 0; q < 4; ++q) {
            float v0 = v[2*q], v1 = v[2*q+1];
            hw[q] = pack_bf16(v0, v1);
            float h0 = __bfloat162float(__ushort_as_bfloat16((unsigned short)(hw[q] & 0xFFFF)));
            float h1 = __bfloat162float(__ushort_as_bfloat16((unsigned short)(hw[q] >> 16)));
            lw[q] = pack_bf16(v0 - h0, v1 - h1);
        }
        *(uint4*)(g_cath + pixg * 128 + 64 + g * 8) = make_uint4(hw[0], hw[1], hw[2], hw[3]);
        *(uint4*)(g_catl + pixg * 128 + 64 + g * 8) = make_uint4(lw[0], lw[1], lw[2], lw[3]);
    }
    if (t < 64 * 9 * 128) {
        int oc = t / (9 * 128), rem = t % (9 * 128);
        int s = rem / 128, c = rem % 128;
        float v = w1[(oc * 128 + c) * 9 + s];
        __nv_bfloat16 h = __float2bfloat16(v);
        g_w1h[(oc * 9 + s) * 128 + c] = h;
        g_w1l[(oc * 9 + s) * 128 + c] = __float2bfloat16(v - __bfloat162float(h));
    }
    if (t < 64 * 9 * 64) {
        int oc = t / (9 * 64), rem = t % (9 * 64);
        int s = rem / 64, c = rem % 64;
        float v = w2[(oc * 64 + c) * 9 + s];
        __nv_bfloat16 h = __float2bfloat16(v);
        g_w2h[(oc * 9 + s) * 64 + c] = h;
        g_w2l[(oc * 9 + s) * 64 + c] = __float2bfloat16(v - __bfloat162float(h));
    }
}

// ---------------------------------------------------------------------------
// Kernel 3: deformable bilinear sampling + modulation + group 3x3 "conv"
// (offsets read coalesced from SoA g_off)
// ---------------------------------------------------------------------------
__global__ __launch_bounds__(256)
void deform_kernel(const float* __restrict__ cw)
{
    __shared__ float cw_s[NPT * CPG * CPG];

    const int tid = threadIdx.x;
    const int bg = blockIdx.y;
    const int b = bg >> 3, g = bg & 7;

    for (int idx = tid; idx < NPT * 64; idx += 256) {
        int n = idx / 64, rem = idx % 64;
        int c = rem / 8, oc = rem % 8;
        cw_s[idx] = cw[(((g * CPG + oc) * CPG + c) * NPT) + n];
    }
    __syncthreads();

    const int pixel = blockIdx.x * 256 + tid;
    const int i = pixel >> 7, j = pixel & (W - 1);

    float offv[27];
    {
        const float* ob = g_off + (size_t)bg * 28 * PIX + pixel;
#pragma unroll
        for (int q = 0; q < 27; ++q) offv[q] = ob[q * PIX];   // coalesced LDG.32
    }

    const float4* xt4 = (const float4*)(g_xt + (size_t)bg * PIX * CPG);

    float acc[8];
#pragma unroll
    for (int oc = 0; oc < 8; ++oc) acc[oc] = 0.f;

#pragma unroll
    for (int n = 0; n < NPT; ++n) {
        const int pnx = n / 3 - 1, pny = n % 3 - 1;
        float px = (float)(i + 1 + pnx) + offv[n];
        float py = (float)(j + 1 + pny) + offv[NPT + n];
        float m  = offv[18 + n];

        float fx = floorf(px), fy = floorf(py);
        float qxl = fminf(fmaxf(fx,       0.f), (float)(H - 1));
        float qxr = fminf(fmaxf(fx + 1.f, 0.f), (float)(H - 1));
        float qyl = fminf(fmaxf(fy,       0.f), (float)(W - 1));
        float qyr = fminf(fmaxf(fy + 1.f, 0.f), (float)(W - 1));
        float pxc = fminf(fmaxf(px, 0.f), (float)(H - 1));
        float pyc = fminf(fmaxf(py, 0.f), (float)(W - 1));

        float glt = (1.f + (qxl - pxc)) * (1.f + (qyl - pyc));
        float grb = (1.f - (qxr - pxc)) * (1.f - (qyr - pyc));
        float glb = (1.f + (qxl - pxc)) * (1.f - (qyr - pyc));
        float grt = (1.f - (qxr - pxc)) * (1.f + (qyl - pyc));

        int ixl = (int)qxl, ixr = (int)qxr, iyl = (int)qyl, iyr = (int)qyr;

        const float4* pa  = xt4 + (((ixl << 7) + iyl) << 1);
        const float4* pb_ = xt4 + (((ixr << 7) + iyr) << 1);
        const float4* pc  = xt4 + (((ixl << 7) + iyr) << 1);
        const float4* pd  = xt4 + (((ixr << 7) + iyl) << 1);

        float av[8], bv[8], cv[8], dv[8];
        *(float4*)&av[0] = pa[0];  *(float4*)&av[4] = pa[1];
        *(float4*)&bv[0] = pb_[0]; *(float4*)&bv[4] = pb_[1];
        *(float4*)&cv[0] = pc[0];  *(float4*)&cv[4] = pc[1];
        *(float4*)&dv[0] = pd[0];  *(float4*)&dv[4] = pd[1];

        const float* wn = cw_s + n * 64;
#pragma unroll
        for (int c = 0; c < CPG; ++c) {
            float vc = fmaf(glt, av[c], fmaf(grb, bv[c], fmaf(glb, cv[c], grt * dv[c]))) * m;
            const float* wr = wn + c * 8;
#pragma unroll
            for (int oc = 0; oc < 8; ++oc)
                acc[oc] = fmaf(vc, wr[oc], acc[oc]);
        }
    }

    size_t pixg = (size_t)b * PIX + pixel;
    *(float4*)(g_tgt + pixg * 64 + g * 8)     = make_float4(acc[0], acc[1], acc[2], acc[3]);
    *(float4*)(g_tgt + pixg * 64 + g * 8 + 4) = make_float4(acc[4], acc[5], acc[6], acc[7]);

    u32 hw[4], lw[4];
#pragma unroll
    for (int q = 0; q < 4; ++q) {
        float v0 = acc[2*q], v1 = acc[2*q+1];
        hw[q] = pack_bf16(v0, v1);
        float h0 = __bfloat162float(__ushort_as_bfloat16((unsigned short)(hw[q] & 0xFFFF)));
        float h1 = __bfloat162float(__ushort_as_bfloat16((unsigned short)(hw[q] >> 16)));
        lw[q] = pack_bf16(v0 - h0, v1 - h1);
    }
    *(uint4*)(g_cath + pixg * 128 + g * 8) = make_uint4(hw[0], hw[1], hw[2], hw[3]);
    *(uint4*)(g_catl + pixg * 128 + g * 8) = make_uint4(lw[0], lw[1], lw[2], lw[3]);
}

// ---------------------------------------------------------------------------
// Kernels 4/5: mma.sync (HMMA) implicit-GEMM 3x3 conv, split-bf16, fp32 acc.
// CTA = one image row: M=128 px, N=64 oc, 4 warps (M=32 each), 128 threads.
// B is [oc][cin] row-major = col-major KxN: NON-trans ldmatrix.
// ---------------------------------------------------------------------------
#define ASTRIDE_B 144          // 72 bf16
#define AL_OFF    18432        // bytes
#define BH_OFF    36864
#define BL_OFF    46080
#define BUF_BYTES 55296
#define DSMEM_BYTES (2*BUF_BYTES)

template <int MODE>
__global__ __launch_bounds__(128)
void conv_mma(const float* __restrict__ bias, float* __restrict__ out)
{
    constexpr int CINT = (MODE == 0) ? 128 : 64;
    constexpr int S = (MODE == 0) ? 18 : 9;

    extern __shared__ __align__(128) char dsm[];
    __shared__ float bsm[64];

    const u32 sbase = smem_u32(dsm);
    const int tid = threadIdx.x;
    const int lane = tid & 31;
    const int w = tid >> 5;
    const int y = blockIdx.x;
    const int bb = blockIdx.y;

    const __nv_bfloat16* SRC_H = (MODE == 0) ? g_cath : g_midh;
    const __nv_bfloat16* SRC_L = (MODE == 0) ? g_catl : g_midl;
    const __nv_bfloat16* WT_H  = (MODE == 0) ? g_w1h : g_w2h;
    const __nv_bfloat16* WT_L  = (MODE == 0) ? g_w1l : g_w2l;

    if (tid < 64) bsm[tid] = bias[tid];

    auto issue = [&](int s, int buf) {
        int cb = s / 9, tap = s % 9;
        int sy = tap / 3, sx = tap % 3;
        int gy = y + sy - 1;
        u32 bufoff = (u32)buf * BUF_BYTES;
        {
            int gx = tid + sx - 1;
            bool ok = (gy >= 0 && gy < H && gx >= 0 && gx < W);
            int gyc = min(max(gy, 0), H - 1);
            int gxc = min(max(gx, 0), W - 1);
            size_t gp = ((size_t)bb * PIX + (size_t)gyc * W + gxc) * CINT + cb * 64;
            const __nv_bfloat16* sh = SRC_H + gp;
            const __nv_bfloat16* sl = SRC_L + gp;
            u32 dh = sbase + bufoff + (u32)tid * ASTRIDE_B;
            u32 dl = dh + AL_OFF;
            u32 sz = ok ? 16u : 0u;
#pragma unroll
            for (int i = 0; i < 8; ++i) {
                cpa16(dh + i * 16, sh + i * 8, sz);
                cpa16(dl + i * 16, sl + i * 8, sz);
            }
        }
        {
            int oc = tid >> 1, half = tid & 1;
            size_t wp = ((size_t)oc * 9 + tap) * CINT + cb * 64 + half * 32;
            u32 dh = sbase + bufoff + BH_OFF + (u32)oc * ASTRIDE_B + (u32)half * 64;
            u32 dl = dh + (BL_OFF - BH_OFF);
#pragma unroll
            for (int i = 0; i < 4; ++i) {
                cpa16(dh + i * 16, WT_H + wp + i * 8, 16u);
                cpa16(dl + i * 16, WT_L + wp + i * 8, 16u);
            }
        }
        cp_commit();
    };

    float acc[2][8][4];
#pragma unroll
    for (int mt = 0; mt < 2; ++mt)
#pragma unroll
        for (int nt = 0; nt < 8; ++nt)
#pragma unroll
            for (int c = 0; c < 4; ++c) acc[mt][nt][c] = 0.f;

    const u32 qoff = (u32)(lane & 15) * ASTRIDE_B + (u32)(lane >> 4) * 16;

    issue(0, 0);

    for (int s = 0; s < S; ++s) {
        const int buf = s & 1;
        if (s + 1 < S) { issue(s + 1, buf ^ 1); cp_wait1(); }
        else           { cp_wait0(); }
        __syncthreads();

        const u32 aBase = sbase + (u32)buf * BUF_BYTES;
        const u32 bBase = aBase + BH_OFF;

#pragma unroll
        for (int kk = 0; kk < 4; ++kk) {
            u32 ah[2][4], al[2][4];
#pragma unroll
            for (int mt = 0; mt < 2; ++mt) {
                u32 rowb = (u32)(w * 32 + mt * 16) * ASTRIDE_B + (u32)kk * 32 + qoff;
                ldm4(ah[mt], aBase + rowb);
                ldm4(al[mt], aBase + AL_OFF + rowb);
            }
            u32 bh[4][4], bl[4][4];
#pragma unroll
            for (int nt2 = 0; nt2 < 4; ++nt2) {
                u32 rowb = (u32)(nt2 * 16) * ASTRIDE_B + (u32)kk * 32 + qoff;
                ldm4(bh[nt2], bBase + rowb);
                ldm4(bl[nt2], bBase + (BL_OFF - BH_OFF) + rowb);
            }
#pragma unroll
            for (int mt = 0; mt < 2; ++mt) {
#pragma unroll
                for (int nt = 0; nt < 8; ++nt) {
                    int nt2 = nt >> 1, odd = nt & 1;
                    u32 b0h = bh[nt2][odd], b1h = bh[nt2][odd + 2];
                    mma16816(acc[mt][nt], ah[mt], b0h, b1h);   // wh * xh
                    mma16816(acc[mt][nt], al[mt], b0h, b1h);   // wh * xl
                    u32 b0l = bl[nt2][odd], b1l = bl[nt2][odd + 2];
                    mma16816(acc[mt][nt], ah[mt], b0l, b1l);   // wl * xh
                }
            }
        }
        __syncthreads();
    }

    const int r0 = lane >> 2;
    const int cp2 = (lane & 3) * 2;

#pragma unroll
    for (int mt = 0; mt < 2; ++mt) {
#pragma unroll
        for (int hh = 0; hh < 2; ++hh) {
            int px = w * 32 + mt * 16 + r0 + hh * 8;
            size_t pixoff = (size_t)y * W + px;
            if (MODE == 0) {
                size_t pg = ((size_t)bb * PIX + pixoff) * 64;
#pragma unroll
                for (int nt = 0; nt < 8; ++nt) {
                    int col = nt * 8 + cp2;
                    float v0 = acc[mt][nt][hh * 2]     + bsm[col];
                    float v1 = acc[mt][nt][hh * 2 + 1] + bsm[col + 1];
                    u32 hw = pack_bf16(v0, v1);
                    float h0 = __bfloat162float(__ushort_as_bfloat16((unsigned short)(hw & 0xFFFF)));
                    float h1 = __bfloat162float(__ushort_as_bfloat16((unsigned short)(hw >> 16)));
                    u32 lw = pack_bf16(v0 - h0, v1 - h1);
                    *(u32*)(g_midh + pg + col) = hw;
                    *(u32*)(g_midl + pg + col) = lw;
                }
            } else {
                const float* tg = g_tgt + ((size_t)bb * PIX + pixoff) * 64;
#pragma unroll
                for (int nt = 0; nt < 8; ++nt) {
                    int col = nt * 8 + cp2;
                    float v0 = acc[mt][nt][hh * 2]     + bsm[col]     + tg[col];
                    float v1 = acc[mt][nt][hh * 2 + 1] + bsm[col + 1] + tg[col + 1];
                    out[((size_t)(bb * 64 + col)) * PIX + pixoff] = v0;
                    out[((size_t)(bb * 64 + col + 1)) * PIX + pixoff] = v1;
                }
            }
        }
    }
}

// ---------------------------------------------------------------------------
extern "C" void kernel_launch(void* const* d_in, const int* in_sizes, int n_in,
                              void* d_out, int out_size)
{
    const float* o      = (const float*)d_in[0];
    const float* anchor = (const float*)d_in[1];
    const float* pw     = (const float*)d_in[2];
    const float* pb     = (const float*)d_in[3];
    const float* mw     = (const float*)d_in[4];
    const float* mb     = (const float*)d_in[5];
    const float* cw     = (const float*)d_in[6];
    const float* w1     = (const float*)d_in[7];
    const float* b1     = (const float*)d_in[8];
    const float* w2     = (const float*)d_in[9];
    const float* b2     = (const float*)d_in[10];
    float* out = (float*)d_out;

    cudaFuncSetAttribute(conv_mma<0>, cudaFuncAttributeMaxDynamicSharedMemorySize, DSMEM_BYTES);
    cudaFuncSetAttribute(conv_mma<1>, cudaFuncAttributeMaxDynamicSharedMemorySize, DSMEM_BYTES);

    offset_mask_conv<<<dim3(8, 8, B * G), 256>>>(o, pw, pb, mw, mb);
    prep_data<<<(B * G * PIX + 255) / 256, 256>>>(anchor, w1, w2);
    deform_kernel<<<dim3(PIX / 256, B * G), 256>>>(cw);

    conv_mma<0><<<dim3(H, B), 128, DSMEM_BYTES>>>(b1, nullptr);
    conv_mma<1><<<dim3(H, B), 128, DSMEM_BYTES>>>(b2, out);
}

// round 13
// speedup vs baseline: 1.0664x; 1.0187x over previous
#include <cuda_runtime.h>
#include <cuda_bf16.h>
#include <math.h>

// Problem constants
#define B   4
#define C   64
#define H   128
#define W   128
#define G   8
#define CPG 8
#define NPT 9
#define PIX (H*W)

typedef unsigned long long u64;
typedef unsigned int u32;

// ---------------------------------------------------------------------------
// Static device scratch
// ---------------------------------------------------------------------------
__device__ __align__(16) float g_xt[B*G*PIX*CPG];         // anchor (b,g,pix,c)
__device__ __align__(16) float g_off[B*G*28*PIX];         // SoA: [bg][28][pix]
__device__ __align__(16) float g_tgt[B*PIX*64];           // deform out NHWC fp32
__device__ __align__(16) __nv_bfloat16 g_cath[B*PIX*128]; // cat(target,anchor) hi
__device__ __align__(16) __nv_bfloat16 g_catl[B*PIX*128]; // lo
__device__ __align__(16) __nv_bfloat16 g_midh[B*PIX*64];  // conv1 out hi
__device__ __align__(16) __nv_bfloat16 g_midl[B*PIX*64];  // lo
__device__ __align__(16) __nv_bfloat16 g_w1h[64*9*128];   // w1 [oc][tap][cin]
__device__ __align__(16) __nv_bfloat16 g_w1l[64*9*128];
__device__ __align__(16) __nv_bfloat16 g_w2h[64*9*64];
__device__ __align__(16) __nv_bfloat16 g_w2l[64*9*64];

// ---------------------------------------------------------------------------
// PTX helpers (sm_80-class only — compute_103-safe)
// ---------------------------------------------------------------------------
__device__ __forceinline__ u32 smem_u32(const void* p) {
    u32 a;
    asm("{ .reg .u64 t; cvta.to.shared.u64 t, %1; cvt.u32.u64 %0, t; }" : "=r"(a) : "l"(p));
    return a;
}
__device__ __forceinline__ void cpa16(u32 dst, const void* src, u32 sz) {
    asm volatile("cp.async.cg.shared.global [%0], [%1], 16, %2;"
                 :: "r"(dst), "l"(src), "r"(sz));
}
__device__ __forceinline__ void cp_commit() { asm volatile("cp.async.commit_group;"); }
__device__ __forceinline__ void cp_wait1()  { asm volatile("cp.async.wait_group 1;" ::: "memory"); }
__device__ __forceinline__ void cp_wait0()  { asm volatile("cp.async.wait_group 0;" ::: "memory"); }

__device__ __forceinline__ void ldm4(u32* r, u32 a) {
    asm volatile("ldmatrix.sync.aligned.m8n8.x4.shared.b16 {%0,%1,%2,%3}, [%4];"
                 : "=r"(r[0]), "=r"(r[1]), "=r"(r[2]), "=r"(r[3]) : "r"(a));
}
__device__ __forceinline__ void mma16816(float* d, const u32* a, u32 b0, u32 b1) {
    asm volatile(
        "mma.sync.aligned.m16n8k16.row.col.f32.bf16.bf16.f32 "
        "{%0,%1,%2,%3}, {%4,%5,%6,%7}, {%8,%9}, {%0,%1,%2,%3};"
        : "+f"(d[0]), "+f"(d[1]), "+f"(d[2]), "+f"(d[3])
        : "r"(a[0]), "r"(a[1]), "r"(a[2]), "r"(a[3]), "r"(b0), "r"(b1));
}
__device__ __forceinline__ u32 pack_bf16(float a, float b) {
    __nv_bfloat16 ha = __float2bfloat16(a), hb = __float2bfloat16(b);
    return (u32)__bfloat16_as_ushort(ha) | ((u32)__bfloat16_as_ushort(hb) << 16);
}
#define FMA2(acc, a, b) asm("fma.rn.f32x2 %0, %1, %2, %0;" : "+l"(acc) : "l"(a), "l"(b))
#define PACK_DUP(out, x) asm("mov.b64 %0, {%1, %1};" : "=l"(out) : "r"(__float_as_uint(x)))
#define UNPACK2(lo, hi, v) asm("mov.b64 {%0, %1}, %2;" : "=r"(lo), "=r"(hi) : "l"(v))

// ---------------------------------------------------------------------------
// Kernel 1: fused offset-conv (18ch) + mask-conv (9ch) + sigmoid, FFMA2 accs,
// SoA output. grid (8, 8, B*G), block 256.
// ---------------------------------------------------------------------------
__global__ __launch_bounds__(256)
void offset_mask_conv(const float* __restrict__ o,
                      const float* __restrict__ pw, const float* __restrict__ pb,
                      const float* __restrict__ mw, const float* __restrict__ mb)
{
    __shared__ __align__(16) float tsm[CPG * 18 * 18];
    __shared__ __align__(16) float wsm[72 * 28];   // padded stride 28
    __shared__ __align__(16) float bsm[28];

    const int tid = threadIdx.x;
    const int tx = tid & 15, ty = tid >> 4;
    const int bg = blockIdx.z;
    const int b = bg >> 3, g = bg & 7;
    const int row0 = blockIdx.y * 16, col0 = blockIdx.x * 16;

    for (int idx = tid; idx < 72 * 28; idx += 256) {
        int ck = idx / 28, oc = idx % 28;
        int c = ck / 9, k = ck % 9;
        float v = 0.f;
        if (oc < 18)      v = pw[((g * 18 + oc) * CPG + c) * 9 + k];
        else if (oc < 27) v = mw[((g * 9 + (oc - 18)) * CPG + c) * 9 + k];
        wsm[idx] = v;
    }
    if (tid < 28) bsm[tid] = (tid < 18) ? pb[g * 18 + tid]
                           : (tid < 27) ? mb[g * 9 + (tid - 18)] : 0.f;

    const float* src = o + ((size_t)(b * C + g * CPG)) * PIX;
    for (int idx = tid; idx < CPG * 324; idx += 256) {
        int c = idx / 324, rem = idx % 324;
        int rr = rem / 18, cc = rem % 18;
        int gy = row0 + rr - 1, gx = col0 + cc - 1;
        float v = 0.f;
        if (gy >= 0 && gy < H && gx >= 0 && gx < W)
            v = src[c * PIX + gy * W + gx];
        tsm[idx] = v;
    }
    __syncthreads();

    u64 acc2[14];
    {
        const u64* bp = (const u64*)bsm;
#pragma unroll
        for (int q = 0; q < 14; ++q) acc2[q] = bp[q];
    }

#pragma unroll
    for (int c = 0; c < CPG; ++c) {
#pragma unroll
        for (int ky = 0; ky < 3; ++ky) {
#pragma unroll
            for (int kx = 0; kx < 3; ++kx) {
                float xv = tsm[c * 324 + (ty + ky) * 18 + (tx + kx)];
                u64 xb; PACK_DUP(xb, xv);
                const u64* wr = (const u64*)(wsm + (c * 9 + ky * 3 + kx) * 28);
#pragma unroll
                for (int q = 0; q < 14; ++q)
                    FMA2(acc2[q], wr[q], xb);
            }
        }
    }

    float acc[28];
#pragma unroll
    for (int q = 0; q < 14; ++q) {
        u32 lo, hi;
        UNPACK2(lo, hi, acc2[q]);
        acc[2*q] = __uint_as_float(lo);
        acc[2*q+1] = __uint_as_float(hi);
    }

    const int y = row0 + ty, x = col0 + tx;
    float* op = g_off + (size_t)bg * 28 * PIX + y * W + x;   // SoA: stride PIX
#pragma unroll
    for (int oc = 0; oc < 18; ++oc) op[oc * PIX] = acc[oc];
#pragma unroll
    for (int oc = 18; oc < 27; ++oc) op[oc * PIX] = 1.f / (1.f + expf(-acc[oc]));
}

// ---------------------------------------------------------------------------
// Kernel 2: anchor transpose + cat split, AND weight transpose + split.
// ---------------------------------------------------------------------------
__global__ __launch_bounds__(256)
void prep_data(const float* __restrict__ anchor,
               const float* __restrict__ w1, const float* __restrict__ w2)
{
    int t = blockIdx.x * 256 + threadIdx.x;
    if (t < B * G * PIX) {
        int pix = t & (PIX - 1);
        int bg = t >> 14;
        int b = bg >> 3, g = bg & 7;
        const float* src = anchor + ((size_t)(b * C + g * CPG)) * PIX + pix;
        float v[8];
#pragma unroll
        for (int c = 0; c < CPG; ++c) v[c] = src[c * PIX];
#pragma unroll
        for (int c = 0; c < CPG; ++c) g_xt[(size_t)t * CPG + c] = v[c];

        size_t pixg = (size_t)b * PIX + pix;
        u32 hw[4], lw[4];
#pragma unroll
        for (int q = 0; q < 4; ++q) {
            float v0 = v[2*q], v1 = v[2*q+1];
            hw[q] = pack_bf16(v0, v1);
            float h0 = __bfloat162float(__ushort_as_bfloat16((unsigned short)(hw[q] & 0xFFFF)));
            float h1 = __bfloat162float(__ushort_as_bfloat16((unsigned short)(hw[q] >> 16)));
            lw[q] = pack_bf16(v0 - h0, v1 - h1);
        }
        *(uint4*)(g_cath + pixg * 128 + 64 + g * 8) = make_uint4(hw[0], hw[1], hw[2], hw[3]);
        *(uint4*)(g_catl + pixg * 128 + 64 + g * 8) = make_uint4(lw[0], lw[1], lw[2], lw[3]);
    }
    if (t < 64 * 9 * 128) {
        int oc = t / (9 * 128), rem = t % (9 * 128);
        int s = rem / 128, c = rem % 128;
        float v = w1[(oc * 128 + c) * 9 + s];
        __nv_bfloat16 h = __float2bfloat16(v);
        g_w1h[(oc * 9 + s) * 128 + c] = h;
        g_w1l[(oc * 9 + s) * 128 + c] = __float2bfloat16(v - __bfloat162float(h));
    }
    if (t < 64 * 9 * 64) {
        int oc = t / (9 * 64), rem = t % (9 * 64);
        int s = rem / 64, c = rem % 64;
        float v = w2[(oc * 64 + c) * 9 + s];
        __nv_bfloat16 h = __float2bfloat16(v);
        g_w2h[(oc * 9 + s) * 64 + c] = h;
        g_w2l[(oc * 9 + s) * 64 + c] = __float2bfloat16(v - __bfloat162float(h));
    }
}

// ---------------------------------------------------------------------------
// Kernel 3: deformable bilinear sampling + modulation + group 3x3 "conv"
// ---------------------------------------------------------------------------
__global__ __launch_bounds__(256)
void deform_kernel(const float* __restrict__ cw)
{
    __shared__ float cw_s[NPT * CPG * CPG];

    const int tid = threadIdx.x;
    const int bg = blockIdx.y;
    const int b = bg >> 3, g = bg & 7;

    for (int idx = tid; idx < NPT * 64; idx += 256) {
        int n = idx / 64, rem = idx % 64;
        int c = rem / 8, oc = rem % 8;
        cw_s[idx] = cw[(((g * CPG + oc) * CPG + c) * NPT) + n];
    }
    __syncthreads();

    const int pixel = blockIdx.x * 256 + tid;
    const int i = pixel >> 7, j = pixel & (W - 1);

    float offv[27];
    {
        const float* ob = g_off + (size_t)bg * 28 * PIX + pixel;
#pragma unroll
        for (int q = 0; q < 27; ++q) offv[q] = ob[q * PIX];   // coalesced LDG.32
    }

    const float4* xt4 = (const float4*)(g_xt + (size_t)bg * PIX * CPG);

    float acc[8];
#pragma unroll
    for (int oc = 0; oc < 8; ++oc) acc[oc] = 0.f;

#pragma unroll
    for (int n = 0; n < NPT; ++n) {
        const int pnx = n / 3 - 1, pny = n % 3 - 1;
        float px = (float)(i + 1 + pnx) + offv[n];
        float py = (float)(j + 1 + pny) + offv[NPT + n];
        float m  = offv[18 + n];

        float fx = floorf(px), fy = floorf(py);
        float qxl = fminf(fmaxf(fx,       0.f), (float)(H - 1));
        float qxr = fminf(fmaxf(fx + 1.f, 0.f), (float)(H - 1));
        float qyl = fminf(fmaxf(fy,       0.f), (float)(W - 1));
        float qyr = fminf(fmaxf(fy + 1.f, 0.f), (float)(W - 1));
        float pxc = fminf(fmaxf(px, 0.f), (float)(H - 1));
        float pyc = fminf(fmaxf(py, 0.f), (float)(W - 1));

        float glt = (1.f + (qxl - pxc)) * (1.f + (qyl - pyc));
        float grb = (1.f - (qxr - pxc)) * (1.f - (qyr - pyc));
        float glb = (1.f + (qxl - pxc)) * (1.f - (qyr - pyc));
        float grt = (1.f - (qxr - pxc)) * (1.f + (qyl - pyc));

        int ixl = (int)qxl, ixr = (int)qxr, iyl = (int)qyl, iyr = (int)qyr;

        const float4* pa  = xt4 + (((ixl << 7) + iyl) << 1);
        const float4* pb_ = xt4 + (((ixr << 7) + iyr) << 1);
        const float4* pc  = xt4 + (((ixl << 7) + iyr) << 1);
        const float4* pd  = xt4 + (((ixr << 7) + iyl) << 1);

        float av[8], bv[8], cv[8], dv[8];
        *(float4*)&av[0] = pa[0];  *(float4*)&av[4] = pa[1];
        *(float4*)&bv[0] = pb_[0]; *(float4*)&bv[4] = pb_[1];
        *(float4*)&cv[0] = pc[0];  *(float4*)&cv[4] = pc[1];
        *(float4*)&dv[0] = pd[0];  *(float4*)&dv[4] = pd[1];

        const float* wn = cw_s + n * 64;
#pragma unroll
        for (int c = 0; c < CPG; ++c) {
            float vc = fmaf(glt, av[c], fmaf(grb, bv[c], fmaf(glb, cv[c], grt * dv[c]))) * m;
            const float* wr = wn + c * 8;
#pragma unroll
            for (int oc = 0; oc < 8; ++oc)
                acc[oc] = fmaf(vc, wr[oc], acc[oc]);
        }
    }

    size_t pixg = (size_t)b * PIX + pixel;
    *(float4*)(g_tgt + pixg * 64 + g * 8)     = make_float4(acc[0], acc[1], acc[2], acc[3]);
    *(float4*)(g_tgt + pixg * 64 + g * 8 + 4) = make_float4(acc[4], acc[5], acc[6], acc[7]);

    u32 hw[4], lw[4];
#pragma unroll
    for (int q = 0; q < 4; ++q) {
        float v0 = acc[2*q], v1 = acc[2*q+1];
        hw[q] = pack_bf16(v0, v1);
        float h0 = __bfloat162float(__ushort_as_bfloat16((unsigned short)(hw[q] & 0xFFFF)));
        float h1 = __bfloat162float(__ushort_as_bfloat16((unsigned short)(hw[q] >> 16)));
        lw[q] = pack_bf16(v0 - h0, v1 - h1);
    }
    *(uint4*)(g_cath + pixg * 128 + g * 8) = make_uint4(hw[0], hw[1], hw[2], hw[3]);
    *(uint4*)(g_catl + pixg * 128 + g * 8) = make_uint4(lw[0], lw[1], lw[2], lw[3]);
}

// ---------------------------------------------------------------------------
// Kernels 4/5: mma.sync implicit-GEMM 3x3 conv, split-bf16, fp32 acc.
// CTA = one image row, 256 threads / 8 warps, N-SPLIT:
//   warp w: wm = w&3 -> px [wm*32, wm*32+32), wn = w>>2 -> oc [wn*32, wn*32+32)
// Stages: cin-block(64) x 9 taps, cp.async double-buffered. Same smem as R12.
// ---------------------------------------------------------------------------
#define ASTRIDE_B 144          // 72 bf16
#define AL_OFF    18432        // bytes
#define BH_OFF    36864
#define BL_OFF    46080
#define BUF_BYTES 55296
#define DSMEM_BYTES (2*BUF_BYTES)

template <int MODE>
__global__ __launch_bounds__(256)
void conv_mma(const float* __restrict__ bias, float* __restrict__ out)
{
    constexpr int CINT = (MODE == 0) ? 128 : 64;
    constexpr int S = (MODE == 0) ? 18 : 9;

    extern __shared__ __align__(128) char dsm[];
    __shared__ float bsm[64];

    const u32 sbase = smem_u32(dsm);
    const int tid = threadIdx.x;
    const int lane = tid & 31;
    const int w = tid >> 5;
    const int wm = w & 3;          // m-position (32 px)
    const int wn = w >> 2;         // n-half (32 oc)
    const int y = blockIdx.x;
    const int bb = blockIdx.y;

    const __nv_bfloat16* SRC_H = (MODE == 0) ? g_cath : g_midh;
    const __nv_bfloat16* SRC_L = (MODE == 0) ? g_catl : g_midl;
    const __nv_bfloat16* WT_H  = (MODE == 0) ? g_w1h : g_w2h;
    const __nv_bfloat16* WT_L  = (MODE == 0) ? g_w1l : g_w2l;

    if (tid < 64) bsm[tid] = bias[tid];

    // ---- stage loader: 256 threads ----
    //  A: thread t -> pixel row (t & 127), part (t >> 7): 8 x cp.async 16B
    //  B: thread t -> oc (t >> 2), sel (t & 3): part=sel>>1, half=sel&1: 4 x 16B
    auto issue = [&](int s, int buf) {
        int cb = s / 9, tap = s % 9;
        int sy = tap / 3, sx = tap % 3;
        int gy = y + sy - 1;
        u32 bufoff = (u32)buf * BUF_BYTES;
        {
            int row = tid & 127, part = tid >> 7;
            int gx = row + sx - 1;
            bool ok = (gy >= 0 && gy < H && gx >= 0 && gx < W);
            int gyc = min(max(gy, 0), H - 1);
            int gxc = min(max(gx, 0), W - 1);
            size_t gp = ((size_t)bb * PIX + (size_t)gyc * W + gxc) * CINT + cb * 64;
            const __nv_bfloat16* sp = (part ? SRC_L : SRC_H) + gp;
            u32 d = sbase + bufoff + (u32)row * ASTRIDE_B + (part ? AL_OFF : 0);
            u32 sz = ok ? 16u : 0u;
#pragma unroll
            for (int i = 0; i < 8; ++i)
                cpa16(d + i * 16, sp + i * 8, sz);
        }
        {
            int oc = tid >> 2, sel = tid & 3;
            int part = sel >> 1, half = sel & 1;
            size_t wp = ((size_t)oc * 9 + tap) * CINT + cb * 64 + half * 32;
            const __nv_bfloat16* sp = (part ? WT_L : WT_H) + wp;
            u32 d = sbase + bufoff + (part ? BL_OFF : BH_OFF)
                  + (u32)oc * ASTRIDE_B + (u32)half * 64;
#pragma unroll
            for (int i = 0; i < 4; ++i)
                cpa16(d + i * 16, sp + i * 8, 16u);
        }
        cp_commit();
    };

    float acc[2][4][4];
#pragma unroll
    for (int mt = 0; mt < 2; ++mt)
#pragma unroll
        for (int nt = 0; nt < 4; ++nt)
#pragma unroll
            for (int c = 0; c < 4; ++c) acc[mt][nt][c] = 0.f;

    const u32 qoff = (u32)(lane & 15) * ASTRIDE_B + (u32)(lane >> 4) * 16;

    issue(0, 0);

    for (int s = 0; s < S; ++s) {
        const int buf = s & 1;
        if (s + 1 < S) { issue(s + 1, buf ^ 1); cp_wait1(); }
        else           { cp_wait0(); }
        __syncthreads();

        const u32 aBase = sbase + (u32)buf * BUF_BYTES;
        const u32 bBase = aBase + BH_OFF;

#pragma unroll
        for (int kk = 0; kk < 4; ++kk) {
            u32 ah[2][4], al[2][4];
#pragma unroll
            for (int mt = 0; mt < 2; ++mt) {
                u32 rowb = (u32)(wm * 32 + mt * 16) * ASTRIDE_B + (u32)kk * 32 + qoff;
                ldm4(ah[mt], aBase + rowb);
                ldm4(al[mt], aBase + AL_OFF + rowb);
            }
            u32 bh[2][4], bl[2][4];
#pragma unroll
            for (int nt2 = 0; nt2 < 2; ++nt2) {
                u32 rowb = (u32)(wn * 32 + nt2 * 16) * ASTRIDE_B + (u32)kk * 32 + qoff;
                ldm4(bh[nt2], bBase + rowb);
                ldm4(bl[nt2], bBase + (BL_OFF - BH_OFF) + rowb);
            }
#pragma unroll
            for (int mt = 0; mt < 2; ++mt) {
#pragma unroll
                for (int nt = 0; nt < 4; ++nt) {
                    int nt2 = nt >> 1, odd = nt & 1;
                    u32 b0h = bh[nt2][odd], b1h = bh[nt2][odd + 2];
                    mma16816(acc[mt][nt], ah[mt], b0h, b1h);   // wh * xh
                    mma16816(acc[mt][nt], al[mt], b0h, b1h);   // wh * xl
                    u32 b0l = bl[nt2][odd], b1l = bl[nt2][odd + 2];
                    mma16816(acc[mt][nt], ah[mt], b0l, b1l);   // wl * xh
                }
            }
        }
        __syncthreads();
    }

    // ---- epilogue ----
    const int r0 = lane >> 2;
    const int cp2 = (lane & 3) * 2;

#pragma unroll
    for (int mt = 0; mt < 2; ++mt) {
#pragma unroll
        for (int hh = 0; hh < 2; ++hh) {
            int px = wm * 32 + mt * 16 + r0 + hh * 8;
            size_t pixoff = (size_t)y * W + px;
            if (MODE == 0) {
                size_t pg = ((size_t)bb * PIX + pixoff) * 64;
#pragma unroll
                for (int nt = 0; nt < 4; ++nt) {
                    int col = wn * 32 + nt * 8 + cp2;
                    float v0 = acc[mt][nt][hh * 2]     + bsm[col];
                    float v1 = acc[mt][nt][hh * 2 + 1] + bsm[col + 1];
                    u32 hw = pack_bf16(v0, v1);
                    float h0 = __bfloat162float(__ushort_as_bfloat16((unsigned short)(hw & 0xFFFF)));
                    float h1 = __bfloat162float(__ushort_as_bfloat16((unsigned short)(hw >> 16)));
                    u32 lw = pack_bf16(v0 - h0, v1 - h1);
                    *(u32*)(g_midh + pg + col) = hw;
                    *(u32*)(g_midl + pg + col) = lw;
                }
            } else {
                const float* tg = g_tgt + ((size_t)bb * PIX + pixoff) * 64;
#pragma unroll
                for (int nt = 0; nt < 4; ++nt) {
                    int col = wn * 32 + nt * 8 + cp2;
                    float v0 = acc[mt][nt][hh * 2]     + bsm[col]     + tg[col];
                    float v1 = acc[mt][nt][hh * 2 + 1] + bsm[col + 1] + tg[col + 1];
                    out[((size_t)(bb * 64 + col)) * PIX + pixoff] = v0;
                    out[((size_t)(bb * 64 + col + 1)) * PIX + pixoff] = v1;
                }
            }
        }
    }
}

// ---------------------------------------------------------------------------
extern "C" void kernel_launch(void* const* d_in, const int* in_sizes, int n_in,
                              void* d_out, int out_size)
{
    const float* o      = (const float*)d_in[0];
    const float* anchor = (const float*)d_in[1];
    const float* pw     = (const float*)d_in[2];
    const float* pb     = (const float*)d_in[3];
    const float* mw     = (const float*)d_in[4];
    const float* mb     = (const float*)d_in[5];
    const float* cw     = (const float*)d_in[6];
    const float* w1     = (const float*)d_in[7];
    const float* b1     = (const float*)d_in[8];
    const float* w2     = (const float*)d_in[9];
    const float* b2     = (const float*)d_in[10];
    float* out = (float*)d_out;

    cudaFuncSetAttribute(conv_mma<0>, cudaFuncAttributeMaxDynamicSharedMemorySize, DSMEM_BYTES);
    cudaFuncSetAttribute(conv_mma<1>, cudaFuncAttributeMaxDynamicSharedMemorySize, DSMEM_BYTES);
    cudaFuncSetAttribute(conv_mma<0>, cudaFuncAttributePreferredSharedMemoryCarveout,
                         cudaSharedmemCarveoutMaxShared);
    cudaFuncSetAttribute(conv_mma<1>, cudaFuncAttributePreferredSharedMemoryCarveout,
                         cudaSharedmemCarveoutMaxShared);

    offset_mask_conv<<<dim3(8, 8, B * G), 256>>>(o, pw, pb, mw, mb);
    prep_data<<<(B * G * PIX + 255) / 256, 256>>>(anchor, w1, w2);
    deform_kernel<<<dim3(PIX / 256, B * G), 256>>>(cw);

    conv_mma<0><<<dim3(H, B), 256, DSMEM_BYTES>>>(b1, nullptr);
    conv_mma<1><<<dim3(H, B), 256, DSMEM_BYTES>>>(b2, out);
}

// round 14
// speedup vs baseline: 1.1912x; 1.1170x over previous
#include <cuda_runtime.h>
#include <cuda_bf16.h>
#include <math.h>

// Problem constants
#define B   4
#define C   64
#define H   128
#define W   128
#define G   8
#define CPG 8
#define NPT 9
#define PIX (H*W)

typedef unsigned long long u64;
typedef unsigned int u32;

// ---------------------------------------------------------------------------
// Static device scratch
// ---------------------------------------------------------------------------
__device__ __align__(16) float g_xt[B*G*PIX*CPG];         // anchor (b,g,pix,c)
__device__ __align__(16) float g_off[B*G*28*PIX];         // SoA: [bg][28][pix]
__device__ __align__(16) float g_tgt[B*PIX*64];           // deform out NHWC fp32
__device__ __align__(16) __nv_bfloat16 g_cath[B*PIX*128]; // cat(target,anchor) hi
__device__ __align__(16) __nv_bfloat16 g_catl[B*PIX*128]; // lo
__device__ __align__(16) __nv_bfloat16 g_midh[B*PIX*64];  // conv1 out hi
__device__ __align__(16) __nv_bfloat16 g_midl[B*PIX*64];  // lo
__device__ __align__(16) __nv_bfloat16 g_w1h[64*9*128];   // w1 [oc][tap][cin]
__device__ __align__(16) __nv_bfloat16 g_w1l[64*9*128];
__device__ __align__(16) __nv_bfloat16 g_w2h[64*9*64];
__device__ __align__(16) __nv_bfloat16 g_w2l[64*9*64];

// ---------------------------------------------------------------------------
// PTX helpers (sm_80-class only — compute_103-safe)
// ---------------------------------------------------------------------------
__device__ __forceinline__ u32 smem_u32(const void* p) {
    u32 a;
    asm("{ .reg .u64 t; cvta.to.shared.u64 t, %1; cvt.u32.u64 %0, t; }" : "=r"(a) : "l"(p));
    return a;
}
__device__ __forceinline__ void cpa16(u32 dst, const void* src, u32 sz) {
    asm volatile("cp.async.cg.shared.global [%0], [%1], 16, %2;"
                 :: "r"(dst), "l"(src), "r"(sz));
}
__device__ __forceinline__ void cp_commit() { asm volatile("cp.async.commit_group;"); }
__device__ __forceinline__ void cp_wait1()  { asm volatile("cp.async.wait_group 1;" ::: "memory"); }
__device__ __forceinline__ void cp_wait0()  { asm volatile("cp.async.wait_group 0;" ::: "memory"); }

__device__ __forceinline__ void ldm4(u32* r, u32 a) {
    asm volatile("ldmatrix.sync.aligned.m8n8.x4.shared.b16 {%0,%1,%2,%3}, [%4];"
                 : "=r"(r[0]), "=r"(r[1]), "=r"(r[2]), "=r"(r[3]) : "r"(a));
}
__device__ __forceinline__ void mma16816(float* d, const u32* a, u32 b0, u32 b1) {
    asm volatile(
        "mma.sync.aligned.m16n8k16.row.col.f32.bf16.bf16.f32 "
        "{%0,%1,%2,%3}, {%4,%5,%6,%7}, {%8,%9}, {%0,%1,%2,%3};"
        : "+f"(d[0]), "+f"(d[1]), "+f"(d[2]), "+f"(d[3])
        : "r"(a[0]), "r"(a[1]), "r"(a[2]), "r"(a[3]), "r"(b0), "r"(b1));
}
__device__ __forceinline__ u32 pack_bf16(float a, float b) {
    __nv_bfloat16 ha = __float2bfloat16(a), hb = __float2bfloat16(b);
    return (u32)__bfloat16_as_ushort(ha) | ((u32)__bfloat16_as_ushort(hb) << 16);
}
#define FMA2(acc, a, b) asm("fma.rn.f32x2 %0, %1, %2, %0;" : "+l"(acc) : "l"(a), "l"(b))
#define PACK_DUP(out, x) asm("mov.b64 %0, {%1, %1};" : "=l"(out) : "r"(__float_as_uint(x)))
#define UNPACK2(lo, hi, v) asm("mov.b64 {%0, %1}, %2;" : "=r"(lo), "=r"(hi) : "l"(v))

// ---------------------------------------------------------------------------
// Kernel 1: fused offset-conv (18ch) + mask-conv (9ch) + sigmoid, FFMA2 accs,
// SoA output. grid (8, 8, B*G), block 256.
// ---------------------------------------------------------------------------
__global__ __launch_bounds__(256)
void offset_mask_conv(const float* __restrict__ o,
                      const float* __restrict__ pw, const float* __restrict__ pb,
                      const float* __restrict__ mw, const float* __restrict__ mb)
{
    __shared__ __align__(16) float tsm[CPG * 18 * 18];
    __shared__ __align__(16) float wsm[72 * 28];   // padded stride 28
    __shared__ __align__(16) float bsm[28];

    const int tid = threadIdx.x;
    const int tx = tid & 15, ty = tid >> 4;
    const int bg = blockIdx.z;
    const int b = bg >> 3, g = bg & 7;
    const int row0 = blockIdx.y * 16, col0 = blockIdx.x * 16;

    for (int idx = tid; idx < 72 * 28; idx += 256) {
        int ck = idx / 28, oc = idx % 28;
        int c = ck / 9, k = ck % 9;
        float v = 0.f;
        if (oc < 18)      v = pw[((g * 18 + oc) * CPG + c) * 9 + k];
        else if (oc < 27) v = mw[((g * 9 + (oc - 18)) * CPG + c) * 9 + k];
        wsm[idx] = v;
    }
    if (tid < 28) bsm[tid] = (tid < 18) ? pb[g * 18 + tid]
                           : (tid < 27) ? mb[g * 9 + (tid - 18)] : 0.f;

    const float* src = o + ((size_t)(b * C + g * CPG)) * PIX;
    for (int idx = tid; idx < CPG * 324; idx += 256) {
        int c = idx / 324, rem = idx % 324;
        int rr = rem / 18, cc = rem % 18;
        int gy = row0 + rr - 1, gx = col0 + cc - 1;
        float v = 0.f;
        if (gy >= 0 && gy < H && gx >= 0 && gx < W)
            v = src[c * PIX + gy * W + gx];
        tsm[idx] = v;
    }
    __syncthreads();

    u64 acc2[14];
    {
        const u64* bp = (const u64*)bsm;
#pragma unroll
        for (int q = 0; q < 14; ++q) acc2[q] = bp[q];
    }

#pragma unroll
    for (int c = 0; c < CPG; ++c) {
#pragma unroll
        for (int ky = 0; ky < 3; ++ky) {
#pragma unroll
            for (int kx = 0; kx < 3; ++kx) {
                float xv = tsm[c * 324 + (ty + ky) * 18 + (tx + kx)];
                u64 xb; PACK_DUP(xb, xv);
                const u64* wr = (const u64*)(wsm + (c * 9 + ky * 3 + kx) * 28);
#pragma unroll
                for (int q = 0; q < 14; ++q)
                    FMA2(acc2[q], wr[q], xb);
            }
        }
    }

    float acc[28];
#pragma unroll
    for (int q = 0; q < 14; ++q) {
        u32 lo, hi;
        UNPACK2(lo, hi, acc2[q]);
        acc[2*q] = __uint_as_float(lo);
        acc[2*q+1] = __uint_as_float(hi);
    }

    const int y = row0 + ty, x = col0 + tx;
    float* op = g_off + (size_t)bg * 28 * PIX + y * W + x;   // SoA: stride PIX
#pragma unroll
    for (int oc = 0; oc < 18; ++oc) op[oc * PIX] = acc[oc];
#pragma unroll
    for (int oc = 18; oc < 27; ++oc) op[oc * PIX] = 1.f / (1.f + expf(-acc[oc]));
}

// ---------------------------------------------------------------------------
// Kernel 2: anchor transpose + cat split, AND weight transpose + split.
// ---------------------------------------------------------------------------
__global__ __launch_bounds__(256)
void prep_data(const float* __restrict__ anchor,
               const float* __restrict__ w1, const float* __restrict__ w2)
{
    int t = blockIdx.x * 256 + threadIdx.x;
    if (t < B * G * PIX) {
        int pix = t & (PIX - 1);
        int bg = t >> 14;
        int b = bg >> 3, g = bg & 7;
        const float* src = anchor + ((size_t)(b * C + g * CPG)) * PIX + pix;
        float v[8];
#pragma unroll
        for (int c = 0; c < CPG; ++c) v[c] = src[c * PIX];
#pragma unroll
        for (int c = 0; c < CPG; ++c) g_xt[(size_t)t * CPG + c] = v[c];

        size_t pixg = (size_t)b * PIX + pix;
        u32 hw[4], lw[4];
#pragma unroll
        for (int q = 0; q < 4; ++q) {
            float v0 = v[2*q], v1 = v[2*q+1];
            hw[q] = pack_bf16(v0, v1);
            float h0 = __bfloat162float(__ushort_as_bfloat16((unsigned short)(hw[q] & 0xFFFF)));
            float h1 = __bfloat162float(__ushort_as_bfloat16((unsigned short)(hw[q] >> 16)));
            lw[q] = pack_bf16(v0 - h0, v1 - h1);
        }
        *(uint4*)(g_cath + pixg * 128 + 64 + g * 8) = make_uint4(hw[0], hw[1], hw[2], hw[3]);
        *(uint4*)(g_catl + pixg * 128 + 64 + g * 8) = make_uint4(lw[0], lw[1], lw[2], lw[3]);
    }
    if (t < 64 * 9 * 128) {
        int oc = t / (9 * 128), rem = t % (9 * 128);
        int s = rem / 128, c = rem % 128;
        float v = w1[(oc * 128 + c) * 9 + s];
        __nv_bfloat16 h = __float2bfloat16(v);
        g_w1h[(oc * 9 + s) * 128 + c] = h;
        g_w1l[(oc * 9 + s) * 128 + c] = __float2bfloat16(v - __bfloat162float(h));
    }
    if (t < 64 * 9 * 64) {
        int oc = t / (9 * 64), rem = t % (9 * 64);
        int s = rem / 64, c = rem % 64;
        float v = w2[(oc * 64 + c) * 9 + s];
        __nv_bfloat16 h = __float2bfloat16(v);
        g_w2h[(oc * 9 + s) * 64 + c] = h;
        g_w2l[(oc * 9 + s) * 64 + c] = __float2bfloat16(v - __bfloat162float(h));
    }
}

// ---------------------------------------------------------------------------
// Kernel 3: deformable bilinear sampling + modulation + group 3x3 "conv"
// ---------------------------------------------------------------------------
__global__ __launch_bounds__(256)
void deform_kernel(const float* __restrict__ cw)
{
    __shared__ float cw_s[NPT * CPG * CPG];

    const int tid = threadIdx.x;
    const int bg = blockIdx.y;
    const int b = bg >> 3, g = bg & 7;

    for (int idx = tid; idx < NPT * 64; idx += 256) {
        int n = idx / 64, rem = idx % 64;
        int c = rem / 8, oc = rem % 8;
        cw_s[idx] = cw[(((g * CPG + oc) * CPG + c) * NPT) + n];
    }
    __syncthreads();

    const int pixel = blockIdx.x * 256 + tid;
    const int i = pixel >> 7, j = pixel & (W - 1);

    float offv[27];
    {
        const float* ob = g_off + (size_t)bg * 28 * PIX + pixel;
#pragma unroll
        for (int q = 0; q < 27; ++q) offv[q] = ob[q * PIX];   // coalesced LDG.32
    }

    const float4* xt4 = (const float4*)(g_xt + (size_t)bg * PIX * CPG);

    float acc[8];
#pragma unroll
    for (int oc = 0; oc < 8; ++oc) acc[oc] = 0.f;

#pragma unroll
    for (int n = 0; n < NPT; ++n) {
        const int pnx = n / 3 - 1, pny = n % 3 - 1;
        float px = (float)(i + 1 + pnx) + offv[n];
        float py = (float)(j + 1 + pny) + offv[NPT + n];
        float m  = offv[18 + n];

        float fx = floorf(px), fy = floorf(py);
        float qxl = fminf(fmaxf(fx,       0.f), (float)(H - 1));
        float qxr = fminf(fmaxf(fx + 1.f, 0.f), (float)(H - 1));
        float qyl = fminf(fmaxf(fy,       0.f), (float)(W - 1));
        float qyr = fminf(fmaxf(fy + 1.f, 0.f), (float)(W - 1));
        float pxc = fminf(fmaxf(px, 0.f), (float)(H - 1));
        float pyc = fminf(fmaxf(py, 0.f), (float)(W - 1));

        float glt = (1.f + (qxl - pxc)) * (1.f + (qyl - pyc));
        float grb = (1.f - (qxr - pxc)) * (1.f - (qyr - pyc));
        float glb = (1.f + (qxl - pxc)) * (1.f - (qyr - pyc));
        float grt = (1.f - (qxr - pxc)) * (1.f + (qyl - pyc));

        int ixl = (int)qxl, ixr = (int)qxr, iyl = (int)qyl, iyr = (int)qyr;

        const float4* pa  = xt4 + (((ixl << 7) + iyl) << 1);
        const float4* pb_ = xt4 + (((ixr << 7) + iyr) << 1);
        const float4* pc  = xt4 + (((ixl << 7) + iyr) << 1);
        const float4* pd  = xt4 + (((ixr << 7) + iyl) << 1);

        float av[8], bv[8], cv[8], dv[8];
        *(float4*)&av[0] = pa[0];  *(float4*)&av[4] = pa[1];
        *(float4*)&bv[0] = pb_[0]; *(float4*)&bv[4] = pb_[1];
        *(float4*)&cv[0] = pc[0];  *(float4*)&cv[4] = pc[1];
        *(float4*)&dv[0] = pd[0];  *(float4*)&dv[4] = pd[1];

        const float* wn = cw_s + n * 64;
#pragma unroll
        for (int c = 0; c < CPG; ++c) {
            float vc = fmaf(glt, av[c], fmaf(grb, bv[c], fmaf(glb, cv[c], grt * dv[c]))) * m;
            const float* wr = wn + c * 8;
#pragma unroll
            for (int oc = 0; oc < 8; ++oc)
                acc[oc] = fmaf(vc, wr[oc], acc[oc]);
        }
    }

    size_t pixg = (size_t)b * PIX + pixel;
    *(float4*)(g_tgt + pixg * 64 + g * 8)     = make_float4(acc[0], acc[1], acc[2], acc[3]);
    *(float4*)(g_tgt + pixg * 64 + g * 8 + 4) = make_float4(acc[4], acc[5], acc[6], acc[7]);

    u32 hw[4], lw[4];
#pragma unroll
    for (int q = 0; q < 4; ++q) {
        float v0 = acc[2*q], v1 = acc[2*q+1];
        hw[q] = pack_bf16(v0, v1);
        float h0 = __bfloat162float(__ushort_as_bfloat16((unsigned short)(hw[q] & 0xFFFF)));
        float h1 = __bfloat162float(__ushort_as_bfloat16((unsigned short)(hw[q] >> 16)));
        lw[q] = pack_bf16(v0 - h0, v1 - h1);
    }
    *(uint4*)(g_cath + pixg * 128 + g * 8) = make_uint4(hw[0], hw[1], hw[2], hw[3]);
    *(uint4*)(g_catl + pixg * 128 + g * 8) = make_uint4(lw[0], lw[1], lw[2], lw[3]);
}

// ---------------------------------------------------------------------------
// Kernels 4/5: mma.sync implicit-GEMM 3x3 conv, split-bf16, fp32 acc.
// TAP-FACTORED STAGING: stage = (cin-block, sy). One extended A row (130 px,
// gx in [-1,128], zero-filled OOB) + 3 B taps staged per stage; the sx shift
// is a pure smem view offset (+sx*ASTRIDE_B on A, +sx*B_TAP on B).
// CTA = one image row, 256 threads / 8 warps, N-split (wm=px quarter, wn=oc half).
// ---------------------------------------------------------------------------
#define ASTRIDE_B 144            // 72 bf16 per pixel-row slot
#define A_ROWS    130
#define A_PART    18720          // 130*144 (hi->lo offset)
#define B_OFF     37440          // 2*A_PART
#define B_TAP     9216           // 64*144 per tap per part
#define B_PART    27648          // 3*B_TAP (hi->lo offset)
#define STAGE_PAD 92800          // 92736 rounded up to 128
#define DSMEM_BYTES (2*STAGE_PAD)

template <int MODE>
__global__ __launch_bounds__(256)
void conv_mma(const float* __restrict__ bias, float* __restrict__ out)
{
    constexpr int CINT = (MODE == 0) ? 128 : 64;
    constexpr int S = 3 * (CINT / 64);       // 6 or 3 stages

    extern __shared__ __align__(128) char dsm[];
    __shared__ float bsm[64];

    const u32 sbase = smem_u32(dsm);
    const int tid = threadIdx.x;
    const int lane = tid & 31;
    const int w = tid >> 5;
    const int wm = w & 3;          // m-position (32 px)
    const int wn = w >> 2;         // n-half (32 oc)
    const int y = blockIdx.x;
    const int bb = blockIdx.y;

    const __nv_bfloat16* SRC_H = (MODE == 0) ? g_cath : g_midh;
    const __nv_bfloat16* SRC_L = (MODE == 0) ? g_catl : g_midl;
    const __nv_bfloat16* WT_H  = (MODE == 0) ? g_w1h : g_w2h;
    const __nv_bfloat16* WT_L  = (MODE == 0) ? g_w1l : g_w2l;

    if (tid < 64) bsm[tid] = bias[tid];

    // ---- stage loader: stage s = (cb = s/3, sy = s%3) ----
    auto issue = [&](int s, int buf) {
        int cb = s / 3, sy = s % 3;
        int gy = y + sy - 1;
        bool rowok = (gy >= 0 && gy < H);
        int gyc = min(max(gy, 0), H - 1);
        u32 bufoff = (u32)buf * STAGE_PAD;
        // A: 130 extended-px rows x 2 parts (260 tasks, 8 x 16B each)
        for (int idx = tid; idx < 260; idx += 256) {
            int row = (idx < 130) ? idx : idx - 130;
            int part = (idx < 130) ? 0 : 1;
            int gx = row - 1;
            bool ok = rowok && gx >= 0 && gx < W;
            int gxc = min(max(gx, 0), W - 1);
            size_t gp = ((size_t)bb * PIX + (size_t)gyc * W + gxc) * CINT + cb * 64;
            const __nv_bfloat16* sp = (part ? SRC_L : SRC_H) + gp;
            u32 d = sbase + bufoff + (u32)row * ASTRIDE_B + (part ? A_PART : 0);
            u32 sz = ok ? 16u : 0u;
#pragma unroll
            for (int i = 0; i < 8; ++i)
                cpa16(d + i * 16, sp + i * 8, sz);
        }
        // B: 3 taps (sy*3 + tp); thread -> oc (tid>>2), sel (tid&3)
        int oc = tid >> 2, sel = tid & 3;
        int part = sel >> 1, half = sel & 1;
#pragma unroll
        for (int tp = 0; tp < 3; ++tp) {
            int tap = sy * 3 + tp;
            size_t wp = ((size_t)oc * 9 + tap) * CINT + cb * 64 + half * 32;
            const __nv_bfloat16* sp = (part ? WT_L : WT_H) + wp;
            u32 d = sbase + bufoff + B_OFF + (u32)tp * B_TAP + (part ? B_PART : 0)
                  + (u32)oc * ASTRIDE_B + (u32)half * 64;
#pragma unroll
            for (int i = 0; i < 4; ++i)
                cpa16(d + i * 16, sp + i * 8, 16u);
        }
        cp_commit();
    };

    float acc[2][4][4];
#pragma unroll
    for (int mt = 0; mt < 2; ++mt)
#pragma unroll
        for (int nt = 0; nt < 4; ++nt)
#pragma unroll
            for (int c = 0; c < 4; ++c) acc[mt][nt][c] = 0.f;

    const u32 qoff = (u32)(lane & 15) * ASTRIDE_B + (u32)(lane >> 4) * 16;

    issue(0, 0);

    for (int s = 0; s < S; ++s) {
        const int buf = s & 1;
        if (s + 1 < S) { issue(s + 1, buf ^ 1); cp_wait1(); }
        else           { cp_wait0(); }
        __syncthreads();

        const u32 aBase0 = sbase + (u32)buf * STAGE_PAD;
        const u32 bBase0 = aBase0 + B_OFF;

#pragma unroll
        for (int sx = 0; sx < 3; ++sx) {
            const u32 aB = aBase0 + (u32)sx * ASTRIDE_B;       // pixel shift
            const u32 bB = bBase0 + (u32)sx * B_TAP;           // tap select
#pragma unroll
            for (int kk = 0; kk < 4; ++kk) {
                u32 ah[2][4], al[2][4];
#pragma unroll
                for (int mt = 0; mt < 2; ++mt) {
                    u32 rowb = (u32)(wm * 32 + mt * 16) * ASTRIDE_B + (u32)kk * 32 + qoff;
                    ldm4(ah[mt], aB + rowb);
                    ldm4(al[mt], aB + A_PART + rowb);
                }
                u32 bh[2][4], bl[2][4];
#pragma unroll
                for (int nt2 = 0; nt2 < 2; ++nt2) {
                    u32 rowb = (u32)(wn * 32 + nt2 * 16) * ASTRIDE_B + (u32)kk * 32 + qoff;
                    ldm4(bh[nt2], bB + rowb);
                    ldm4(bl[nt2], bB + B_PART + rowb);
                }
#pragma unroll
                for (int mt = 0; mt < 2; ++mt) {
#pragma unroll
                    for (int nt = 0; nt < 4; ++nt) {
                        int nt2 = nt >> 1, odd = nt & 1;
                        u32 b0h = bh[nt2][odd], b1h = bh[nt2][odd + 2];
                        mma16816(acc[mt][nt], ah[mt], b0h, b1h);   // wh * xh
                        mma16816(acc[mt][nt], al[mt], b0h, b1h);   // wh * xl
                        u32 b0l = bl[nt2][odd], b1l = bl[nt2][odd + 2];
                        mma16816(acc[mt][nt], ah[mt], b0l, b1l);   // wl * xh
                    }
                }
            }
        }
        __syncthreads();
    }

    // ---- epilogue ----
    const int r0 = lane >> 2;
    const int cp2 = (lane & 3) * 2;

#pragma unroll
    for (int mt = 0; mt < 2; ++mt) {
#pragma unroll
        for (int hh = 0; hh < 2; ++hh) {
            int px = wm * 32 + mt * 16 + r0 + hh * 8;
            size_t pixoff = (size_t)y * W + px;
            if (MODE == 0) {
                size_t pg = ((size_t)bb * PIX + pixoff) * 64;
#pragma unroll
                for (int nt = 0; nt < 4; ++nt) {
                    int col = wn * 32 + nt * 8 + cp2;
                    float v0 = acc[mt][nt][hh * 2]     + bsm[col];
                    float v1 = acc[mt][nt][hh * 2 + 1] + bsm[col + 1];
                    u32 hw = pack_bf16(v0, v1);
                    float h0 = __bfloat162float(__ushort_as_bfloat16((unsigned short)(hw & 0xFFFF)));
                    float h1 = __bfloat162float(__ushort_as_bfloat16((unsigned short)(hw >> 16)));
                    u32 lw = pack_bf16(v0 - h0, v1 - h1);
                    *(u32*)(g_midh + pg + col) = hw;
                    *(u32*)(g_midl + pg + col) = lw;
                }
            } else {
                const float* tg = g_tgt + ((size_t)bb * PIX + pixoff) * 64;
#pragma unroll
                for (int nt = 0; nt < 4; ++nt) {
                    int col = wn * 32 + nt * 8 + cp2;
                    float v0 = acc[mt][nt][hh * 2]     + bsm[col]     + tg[col];
                    float v1 = acc[mt][nt][hh * 2 + 1] + bsm[col + 1] + tg[col + 1];
                    out[((size_t)(bb * 64 + col)) * PIX + pixoff] = v0;
                    out[((size_t)(bb * 64 + col + 1)) * PIX + pixoff] = v1;
                }
            }
        }
    }
}

// ---------------------------------------------------------------------------
extern "C" void kernel_launch(void* const* d_in, const int* in_sizes, int n_in,
                              void* d_out, int out_size)
{
    const float* o      = (const float*)d_in[0];
    const float* anchor = (const float*)d_in[1];
    const float* pw     = (const float*)d_in[2];
    const float* pb     = (const float*)d_in[3];
    const float* mw     = (const float*)d_in[4];
    const float* mb     = (const float*)d_in[5];
    const float* cw     = (const float*)d_in[6];
    const float* w1     = (const float*)d_in[7];
    const float* b1     = (const float*)d_in[8];
    const float* w2     = (const float*)d_in[9];
    const float* b2     = (const float*)d_in[10];
    float* out = (float*)d_out;

    cudaFuncSetAttribute(conv_mma<0>, cudaFuncAttributeMaxDynamicSharedMemorySize, DSMEM_BYTES);
    cudaFuncSetAttribute(conv_mma<1>, cudaFuncAttributeMaxDynamicSharedMemorySize, DSMEM_BYTES);
    cudaFuncSetAttribute(conv_mma<0>, cudaFuncAttributePreferredSharedMemoryCarveout,
                         cudaSharedmemCarveoutMaxShared);
    cudaFuncSetAttribute(conv_mma<1>, cudaFuncAttributePreferredSharedMemoryCarveout,
                         cudaSharedmemCarveoutMaxShared);

    offset_mask_conv<<<dim3(8, 8, B * G), 256>>>(o, pw, pb, mw, mb);
    prep_data<<<(B * G * PIX + 255) / 256, 256>>>(anchor, w1, w2);
    deform_kernel<<<dim3(PIX / 256, B * G), 256>>>(cw);

    conv_mma<0><<<dim3(H, B), 256, DSMEM_BYTES>>>(b1, nullptr);
    conv_mma<1><<<dim3(H, B), 256, DSMEM_BYTES>>>(b2, out);
}

// round 15
// speedup vs baseline: 1.3007x; 1.0919x over previous
#include <cuda_runtime.h>
#include <cuda_bf16.h>
#include <math.h>

// Problem constants
#define B   4
#define C   64
#define H   128
#define W   128
#define G   8
#define CPG 8
#define NPT 9
#define PIX (H*W)

typedef unsigned long long u64;
typedef unsigned int u32;

// ---------------------------------------------------------------------------
// Static device scratch
// ---------------------------------------------------------------------------
__device__ __align__(16) float g_xt[B*G*PIX*CPG];         // anchor (b,g,pix,c)
__device__ __align__(16) float g_off[B*G*28*PIX];         // SoA: [bg][28][pix]
__device__ __align__(16) float g_tgt[B*PIX*64];           // deform out NHWC fp32
__device__ __align__(16) __nv_bfloat16 g_cath[B*PIX*128]; // cat(target,anchor) hi
__device__ __align__(16) __nv_bfloat16 g_catl[B*PIX*128]; // lo
__device__ __align__(16) __nv_bfloat16 g_midh[B*PIX*64];  // conv1 out hi
__device__ __align__(16) __nv_bfloat16 g_midl[B*PIX*64];  // lo
__device__ __align__(16) __nv_bfloat16 g_w1h[64*9*128];   // w1 [oc][tap][cin]
__device__ __align__(16) __nv_bfloat16 g_w1l[64*9*128];
__device__ __align__(16) __nv_bfloat16 g_w2h[64*9*64];
__device__ __align__(16) __nv_bfloat16 g_w2l[64*9*64];

// ---------------------------------------------------------------------------
// PTX helpers (sm_80-class only — compute_103-safe)
// ---------------------------------------------------------------------------
__device__ __forceinline__ u32 smem_u32(const void* p) {
    u32 a;
    asm("{ .reg .u64 t; cvta.to.shared.u64 t, %1; cvt.u32.u64 %0, t; }" : "=r"(a) : "l"(p));
    return a;
}
__device__ __forceinline__ void cpa16(u32 dst, const void* src, u32 sz) {
    asm volatile("cp.async.cg.shared.global [%0], [%1], 16, %2;"
                 :: "r"(dst), "l"(src), "r"(sz));
}
__device__ __forceinline__ void cp_commit() { asm volatile("cp.async.commit_group;"); }
__device__ __forceinline__ void cp_wait1()  { asm volatile("cp.async.wait_group 1;" ::: "memory"); }
__device__ __forceinline__ void cp_wait0()  { asm volatile("cp.async.wait_group 0;" ::: "memory"); }

__device__ __forceinline__ void ldm4(u32* r, u32 a) {
    asm volatile("ldmatrix.sync.aligned.m8n8.x4.shared.b16 {%0,%1,%2,%3}, [%4];"
                 : "=r"(r[0]), "=r"(r[1]), "=r"(r[2]), "=r"(r[3]) : "r"(a));
}
__device__ __forceinline__ void mma16816(float* d, const u32* a, u32 b0, u32 b1) {
    asm volatile(
        "mma.sync.aligned.m16n8k16.row.col.f32.bf16.bf16.f32 "
        "{%0,%1,%2,%3}, {%4,%5,%6,%7}, {%8,%9}, {%0,%1,%2,%3};"
        : "+f"(d[0]), "+f"(d[1]), "+f"(d[2]), "+f"(d[3])
        : "r"(a[0]), "r"(a[1]), "r"(a[2]), "r"(a[3]), "r"(b0), "r"(b1));
}
__device__ __forceinline__ u32 pack_bf16(float a, float b) {
    __nv_bfloat16 ha = __float2bfloat16(a), hb = __float2bfloat16(b);
    return (u32)__bfloat16_as_ushort(ha) | ((u32)__bfloat16_as_ushort(hb) << 16);
}
#define FMA2(acc, a, b) asm("fma.rn.f32x2 %0, %1, %2, %0;" : "+l"(acc) : "l"(a), "l"(b))
#define PACK_DUP(out, x) asm("mov.b64 %0, {%1, %1};" : "=l"(out) : "r"(__float_as_uint(x)))
#define UNPACK2(lo, hi, v) asm("mov.b64 {%0, %1}, %2;" : "=r"(lo), "=r"(hi) : "l"(v))

// ---------------------------------------------------------------------------
// Kernel 1: fused offset-conv (18ch) + mask-conv (9ch) + sigmoid, FFMA2 accs,
// SoA output. grid (8, 8, B*G), block 256.
// ---------------------------------------------------------------------------
__global__ __launch_bounds__(256)
void offset_mask_conv(const float* __restrict__ o,
                      const float* __restrict__ pw, const float* __restrict__ pb,
                      const float* __restrict__ mw, const float* __restrict__ mb)
{
    __shared__ __align__(16) float tsm[CPG * 18 * 18];
    __shared__ __align__(16) float wsm[72 * 28];   // padded stride 28
    __shared__ __align__(16) float bsm[28];

    const int tid = threadIdx.x;
    const int tx = tid & 15, ty = tid >> 4;
    const int bg = blockIdx.z;
    const int b = bg >> 3, g = bg & 7;
    const int row0 = blockIdx.y * 16, col0 = blockIdx.x * 16;

    for (int idx = tid; idx < 72 * 28; idx += 256) {
        int ck = idx / 28, oc = idx % 28;
        int c = ck / 9, k = ck % 9;
        float v = 0.f;
        if (oc < 18)      v = pw[((g * 18 + oc) * CPG + c) * 9 + k];
        else if (oc < 27) v = mw[((g * 9 + (oc - 18)) * CPG + c) * 9 + k];
        wsm[idx] = v;
    }
    if (tid < 28) bsm[tid] = (tid < 18) ? pb[g * 18 + tid]
                           : (tid < 27) ? mb[g * 9 + (tid - 18)] : 0.f;

    const float* src = o + ((size_t)(b * C + g * CPG)) * PIX;
    for (int idx = tid; idx < CPG * 324; idx += 256) {
        int c = idx / 324, rem = idx % 324;
        int rr = rem / 18, cc = rem % 18;
        int gy = row0 + rr - 1, gx = col0 + cc - 1;
        float v = 0.f;
        if (gy >= 0 && gy < H && gx >= 0 && gx < W)
            v = src[c * PIX + gy * W + gx];
        tsm[idx] = v;
    }
    __syncthreads();

    u64 acc2[14];
    {
        const u64* bp = (const u64*)bsm;
#pragma unroll
        for (int q = 0; q < 14; ++q) acc2[q] = bp[q];
    }

#pragma unroll
    for (int c = 0; c < CPG; ++c) {
#pragma unroll
        for (int ky = 0; ky < 3; ++ky) {
#pragma unroll
            for (int kx = 0; kx < 3; ++kx) {
                float xv = tsm[c * 324 + (ty + ky) * 18 + (tx + kx)];
                u64 xb; PACK_DUP(xb, xv);
                const u64* wr = (const u64*)(wsm + (c * 9 + ky * 3 + kx) * 28);
#pragma unroll
                for (int q = 0; q < 14; ++q)
                    FMA2(acc2[q], wr[q], xb);
            }
        }
    }

    float acc[28];
#pragma unroll
    for (int q = 0; q < 14; ++q) {
        u32 lo, hi;
        UNPACK2(lo, hi, acc2[q]);
        acc[2*q] = __uint_as_float(lo);
        acc[2*q+1] = __uint_as_float(hi);
    }

    const int y = row0 + ty, x = col0 + tx;
    float* op = g_off + (size_t)bg * 28 * PIX + y * W + x;   // SoA: stride PIX
#pragma unroll
    for (int oc = 0; oc < 18; ++oc) op[oc * PIX] = acc[oc];
#pragma unroll
    for (int oc = 18; oc < 27; ++oc) op[oc * PIX] = 1.f / (1.f + expf(-acc[oc]));
}

// ---------------------------------------------------------------------------
// Kernel 2: anchor transpose + cat split, AND weight transpose + split.
// ---------------------------------------------------------------------------
__global__ __launch_bounds__(256)
void prep_data(const float* __restrict__ anchor,
               const float* __restrict__ w1, const float* __restrict__ w2)
{
    int t = blockIdx.x * 256 + threadIdx.x;
    if (t < B * G * PIX) {
        int pix = t & (PIX - 1);
        int bg = t >> 14;
        int b = bg >> 3, g = bg & 7;
        const float* src = anchor + ((size_t)(b * C + g * CPG)) * PIX + pix;
        float v[8];
#pragma unroll
        for (int c = 0; c < CPG; ++c) v[c] = src[c * PIX];
#pragma unroll
        for (int c = 0; c < CPG; ++c) g_xt[(size_t)t * CPG + c] = v[c];

        size_t pixg = (size_t)b * PIX + pix;
        u32 hw[4], lw[4];
#pragma unroll
        for (int q = 0; q < 4; ++q) {
            float v0 = v[2*q], v1 = v[2*q+1];
            hw[q] = pack_bf16(v0, v1);
            float h0 = __bfloat162float(__ushort_as_bfloat16((unsigned short)(hw[q] & 0xFFFF)));
            float h1 = __bfloat162float(__ushort_as_bfloat16((unsigned short)(hw[q] >> 16)));
            lw[q] = pack_bf16(v0 - h0, v1 - h1);
        }
        *(uint4*)(g_cath + pixg * 128 + 64 + g * 8) = make_uint4(hw[0], hw[1], hw[2], hw[3]);
        *(uint4*)(g_catl + pixg * 128 + 64 + g * 8) = make_uint4(lw[0], lw[1], lw[2], lw[3]);
    }
    if (t < 64 * 9 * 128) {
        int oc = t / (9 * 128), rem = t % (9 * 128);
        int s = rem / 128, c = rem % 128;
        float v = w1[(oc * 128 + c) * 9 + s];
        __nv_bfloat16 h = __float2bfloat16(v);
        g_w1h[(oc * 9 + s) * 128 + c] = h;
        g_w1l[(oc * 9 + s) * 128 + c] = __float2bfloat16(v - __bfloat162float(h));
    }
    if (t < 64 * 9 * 64) {
        int oc = t / (9 * 64), rem = t % (9 * 64);
        int s = rem / 64, c = rem % 64;
        float v = w2[(oc * 64 + c) * 9 + s];
        __nv_bfloat16 h = __float2bfloat16(v);
        g_w2h[(oc * 9 + s) * 64 + c] = h;
        g_w2l[(oc * 9 + s) * 64 + c] = __float2bfloat16(v - __bfloat162float(h));
    }
}

// ---------------------------------------------------------------------------
// Kernel 3: deformable bilinear sampling + modulation + group 3x3 "conv"
// ---------------------------------------------------------------------------
__global__ __launch_bounds__(256)
void deform_kernel(const float* __restrict__ cw)
{
    __shared__ float cw_s[NPT * CPG * CPG];

    const int tid = threadIdx.x;
    const int bg = blockIdx.y;
    const int b = bg >> 3, g = bg & 7;

    for (int idx = tid; idx < NPT * 64; idx += 256) {
        int n = idx / 64, rem = idx % 64;
        int c = rem / 8, oc = rem % 8;
        cw_s[idx] = cw[(((g * CPG + oc) * CPG + c) * NPT) + n];
    }
    __syncthreads();

    const int pixel = blockIdx.x * 256 + tid;
    const int i = pixel >> 7, j = pixel & (W - 1);

    float offv[27];
    {
        const float* ob = g_off + (size_t)bg * 28 * PIX + pixel;
#pragma unroll
        for (int q = 0; q < 27; ++q) offv[q] = ob[q * PIX];   // coalesced LDG.32
    }

    const float4* xt4 = (const float4*)(g_xt + (size_t)bg * PIX * CPG);

    float acc[8];
#pragma unroll
    for (int oc = 0; oc < 8; ++oc) acc[oc] = 0.f;

#pragma unroll
    for (int n = 0; n < NPT; ++n) {
        const int pnx = n / 3 - 1, pny = n % 3 - 1;
        float px = (float)(i + 1 + pnx) + offv[n];
        float py = (float)(j + 1 + pny) + offv[NPT + n];
        float m  = offv[18 + n];

        float fx = floorf(px), fy = floorf(py);
        float qxl = fminf(fmaxf(fx,       0.f), (float)(H - 1));
        float qxr = fminf(fmaxf(fx + 1.f, 0.f), (float)(H - 1));
        float qyl = fminf(fmaxf(fy,       0.f), (float)(W - 1));
        float qyr = fminf(fmaxf(fy + 1.f, 0.f), (float)(W - 1));
        float pxc = fminf(fmaxf(px, 0.f), (float)(H - 1));
        float pyc = fminf(fmaxf(py, 0.f), (float)(W - 1));

        float glt = (1.f + (qxl - pxc)) * (1.f + (qyl - pyc));
        float grb = (1.f - (qxr - pxc)) * (1.f - (qyr - pyc));
        float glb = (1.f + (qxl - pxc)) * (1.f - (qyr - pyc));
        float grt = (1.f - (qxr - pxc)) * (1.f + (qyl - pyc));

        int ixl = (int)qxl, ixr = (int)qxr, iyl = (int)qyl, iyr = (int)qyr;

        const float4* pa  = xt4 + (((ixl << 7) + iyl) << 1);
        const float4* pb_ = xt4 + (((ixr << 7) + iyr) << 1);
        const float4* pc  = xt4 + (((ixl << 7) + iyr) << 1);
        const float4* pd  = xt4 + (((ixr << 7) + iyl) << 1);

        float av[8], bv[8], cv[8], dv[8];
        *(float4*)&av[0] = pa[0];  *(float4*)&av[4] = pa[1];
        *(float4*)&bv[0] = pb_[0]; *(float4*)&bv[4] = pb_[1];
        *(float4*)&cv[0] = pc[0];  *(float4*)&cv[4] = pc[1];
        *(float4*)&dv[0] = pd[0];  *(float4*)&dv[4] = pd[1];

        const float* wn = cw_s + n * 64;
#pragma unroll
        for (int c = 0; c < CPG; ++c) {
            float vc = fmaf(glt, av[c], fmaf(grb, bv[c], fmaf(glb, cv[c], grt * dv[c]))) * m;
            const float* wr = wn + c * 8;
#pragma unroll
            for (int oc = 0; oc < 8; ++oc)
                acc[oc] = fmaf(vc, wr[oc], acc[oc]);
        }
    }

    size_t pixg = (size_t)b * PIX + pixel;
    *(float4*)(g_tgt + pixg * 64 + g * 8)     = make_float4(acc[0], acc[1], acc[2], acc[3]);
    *(float4*)(g_tgt + pixg * 64 + g * 8 + 4) = make_float4(acc[4], acc[5], acc[6], acc[7]);

    u32 hw[4], lw[4];
#pragma unroll
    for (int q = 0; q < 4; ++q) {
        float v0 = acc[2*q], v1 = acc[2*q+1];
        hw[q] = pack_bf16(v0, v1);
        float h0 = __bfloat162float(__ushort_as_bfloat16((unsigned short)(hw[q] & 0xFFFF)));
        float h1 = __bfloat162float(__ushort_as_bfloat16((unsigned short)(hw[q] >> 16)));
        lw[q] = pack_bf16(v0 - h0, v1 - h1);
    }
    *(uint4*)(g_cath + pixg * 128 + g * 8) = make_uint4(hw[0], hw[1], hw[2], hw[3]);
    *(uint4*)(g_catl + pixg * 128 + g * 8) = make_uint4(lw[0], lw[1], lw[2], lw[3]);
}

// ---------------------------------------------------------------------------
// Kernels 4/5: mma.sync implicit-GEMM 3x3 conv, split-bf16, fp32 acc.
// TAP-FACTORED STAGING with cin-32 stages: stage = (cb32, sy). Stage buffer
// 51.5 KB -> double-buffered 103 KB -> 2 CTAs/SM (latency hiding).
// A slot 80 B/px (32 cin), B 3 taps x 64 oc x 80 B, hi/lo parts.
// sx shift = smem view offset (+sx*80 on A, +sx*B_TAP on B).
// CTA = one image row, 256 threads / 8 warps, N-split (wm=px quarter, wn=oc half).
// ---------------------------------------------------------------------------
#define ASTRIDE_B 80             // 32 cin bf16 (64B) + 16B pad
#define A_PART    10400          // 130*80 (hi->lo offset)
#define B_OFF     20800          // 2*A_PART
#define B_TAP     5120           // 64*80 per tap per part
#define B_PART    15360          // 3*B_TAP (hi->lo offset)
#define STAGE_PAD 51584          // 51520 rounded to 128
#define DSMEM_BYTES (2*STAGE_PAD)

template <int MODE>
__global__ __launch_bounds__(256)
void conv_mma(const float* __restrict__ bias, float* __restrict__ out)
{
    constexpr int CINT = (MODE == 0) ? 128 : 64;
    constexpr int S = 3 * (CINT / 32);       // 12 or 6 stages

    extern __shared__ __align__(128) char dsm[];
    __shared__ float bsm[64];

    const u32 sbase = smem_u32(dsm);
    const int tid = threadIdx.x;
    const int lane = tid & 31;
    const int w = tid >> 5;
    const int wm = w & 3;          // m-position (32 px)
    const int wn = w >> 2;         // n-half (32 oc)
    const int y = blockIdx.x;
    const int bb = blockIdx.y;

    const __nv_bfloat16* SRC_H = (MODE == 0) ? g_cath : g_midh;
    const __nv_bfloat16* SRC_L = (MODE == 0) ? g_catl : g_midl;
    const __nv_bfloat16* WT_H  = (MODE == 0) ? g_w1h : g_w2h;
    const __nv_bfloat16* WT_L  = (MODE == 0) ? g_w1l : g_w2l;

    if (tid < 64) bsm[tid] = bias[tid];

    // ---- stage loader: stage s = (cb = s/3 [cin-32 block], sy = s%3) ----
    auto issue = [&](int s, int buf) {
        int cb = s / 3, sy = s % 3;
        int gy = y + sy - 1;
        bool rowok = (gy >= 0 && gy < H);
        int gyc = min(max(gy, 0), H - 1);
        u32 bufoff = (u32)buf * STAGE_PAD;
        // A: 130 extended-px rows x 2 parts (260 tasks, 4 x 16B each)
        for (int idx = tid; idx < 260; idx += 256) {
            int row = (idx < 130) ? idx : idx - 130;
            int part = (idx < 130) ? 0 : 1;
            int gx = row - 1;
            bool ok = rowok && gx >= 0 && gx < W;
            int gxc = min(max(gx, 0), W - 1);
            size_t gp = ((size_t)bb * PIX + (size_t)gyc * W + gxc) * CINT + cb * 32;
            const __nv_bfloat16* sp = (part ? SRC_L : SRC_H) + gp;
            u32 d = sbase + bufoff + (u32)row * ASTRIDE_B + (part ? A_PART : 0);
            u32 sz = ok ? 16u : 0u;
#pragma unroll
            for (int i = 0; i < 4; ++i)
                cpa16(d + i * 16, sp + i * 8, sz);
        }
        // B: 3 taps (sy*3 + tp); thread -> oc (tid>>2), sel (tid&3)
        int oc = tid >> 2, sel = tid & 3;
        int part = sel >> 1, half = sel & 1;
#pragma unroll
        for (int tp = 0; tp < 3; ++tp) {
            int tap = sy * 3 + tp;
            size_t wp = ((size_t)oc * 9 + tap) * CINT + cb * 32 + half * 16;
            const __nv_bfloat16* sp = (part ? WT_L : WT_H) + wp;
            u32 d = sbase + bufoff + B_OFF + (u32)tp * B_TAP + (part ? B_PART : 0)
                  + (u32)oc * ASTRIDE_B + (u32)half * 32;
#pragma unroll
            for (int i = 0; i < 2; ++i)
                cpa16(d + i * 16, sp + i * 8, 16u);
        }
        cp_commit();
    };

    float acc[2][4][4];
#pragma unroll
    for (int mt = 0; mt < 2; ++mt)
#pragma unroll
        for (int nt = 0; nt < 4; ++nt)
#pragma unroll
            for (int c = 0; c < 4; ++c) acc[mt][nt][c] = 0.f;

    const u32 qoff = (u32)(lane & 15) * ASTRIDE_B + (u32)(lane >> 4) * 16;

    issue(0, 0);

    for (int s = 0; s < S; ++s) {
        const int buf = s & 1;
        if (s + 1 < S) { issue(s + 1, buf ^ 1); cp_wait1(); }
        else           { cp_wait0(); }
        __syncthreads();

        const u32 aBase0 = sbase + (u32)buf * STAGE_PAD;
        const u32 bBase0 = aBase0 + B_OFF;

#pragma unroll
        for (int sx = 0; sx < 3; ++sx) {
            const u32 aB = aBase0 + (u32)sx * ASTRIDE_B;       // pixel shift
            const u32 bB = bBase0 + (u32)sx * B_TAP;           // tap select
#pragma unroll
            for (int kk = 0; kk < 2; ++kk) {
                u32 ah[2][4], al[2][4];
#pragma unroll
                for (int mt = 0; mt < 2; ++mt) {
                    u32 rowb = (u32)(wm * 32 + mt * 16) * ASTRIDE_B + (u32)kk * 32 + qoff;
                    ldm4(ah[mt], aB + rowb);
                    ldm4(al[mt], aB + A_PART + rowb);
                }
                u32 bh[2][4], bl[2][4];
#pragma unroll
                for (int nt2 = 0; nt2 < 2; ++nt2) {
                    u32 rowb = (u32)(wn * 32 + nt2 * 16) * ASTRIDE_B + (u32)kk * 32 + qoff;
                    ldm4(bh[nt2], bB + rowb);
                    ldm4(bl[nt2], bB + B_PART + rowb);
                }
#pragma unroll
                for (int mt = 0; mt < 2; ++mt) {
#pragma unroll
                    for (int nt = 0; nt < 4; ++nt) {
                        int nt2 = nt >> 1, odd = nt & 1;
                        u32 b0h = bh[nt2][odd], b1h = bh[nt2][odd + 2];
                        mma16816(acc[mt][nt], ah[mt], b0h, b1h);   // wh * xh
                        mma16816(acc[mt][nt], al[mt], b0h, b1h);   // wh * xl
                        u32 b0l = bl[nt2][odd], b1l = bl[nt2][odd + 2];
                        mma16816(acc[mt][nt], ah[mt], b0l, b1l);   // wl * xh
                    }
                }
            }
        }
        __syncthreads();
    }

    // ---- epilogue ----
    const int r0 = lane >> 2;
    const int cp2 = (lane & 3) * 2;

#pragma unroll
    for (int mt = 0; mt < 2; ++mt) {
#pragma unroll
        for (int hh = 0; hh < 2; ++hh) {
            int px = wm * 32 + mt * 16 + r0 + hh * 8;
            size_t pixoff = (size_t)y * W + px;
            if (MODE == 0) {
                size_t pg = ((size_t)bb * PIX + pixoff) * 64;
#pragma unroll
                for (int nt = 0; nt < 4; ++nt) {
                    int col = wn * 32 + nt * 8 + cp2;
                    float v0 = acc[mt][nt][hh * 2]     + bsm[col];
                    float v1 = acc[mt][nt][hh * 2 + 1] + bsm[col + 1];
                    u32 hw = pack_bf16(v0, v1);
                    float h0 = __bfloat162float(__ushort_as_bfloat16((unsigned short)(hw & 0xFFFF)));
                    float h1 = __bfloat162float(__ushort_as_bfloat16((unsigned short)(hw >> 16)));
                    u32 lw = pack_bf16(v0 - h0, v1 - h1);
                    *(u32*)(g_midh + pg + col) = hw;
                    *(u32*)(g_midl + pg + col) = lw;
                }
            } else {
                const float* tg = g_tgt + ((size_t)bb * PIX + pixoff) * 64;
#pragma unroll
                for (int nt = 0; nt < 4; ++nt) {
                    int col = wn * 32 + nt * 8 + cp2;
                    float v0 = acc[mt][nt][hh * 2]     + bsm[col]     + tg[col];
                    float v1 = acc[mt][nt][hh * 2 + 1] + bsm[col + 1] + tg[col + 1];
                    out[((size_t)(bb * 64 + col)) * PIX + pixoff] = v0;
                    out[((size_t)(bb * 64 + col + 1)) * PIX + pixoff] = v1;
                }
            }
        }
    }
}

// ---------------------------------------------------------------------------
extern "C" void kernel_launch(void* const* d_in, const int* in_sizes, int n_in,
                              void* d_out, int out_size)
{
    const float* o      = (const float*)d_in[0];
    const float* anchor = (const float*)d_in[1];
    const float* pw     = (const float*)d_in[2];
    const float* pb     = (const float*)d_in[3];
    const float* mw     = (const float*)d_in[4];
    const float* mb     = (const float*)d_in[5];
    const float* cw     = (const float*)d_in[6];
    const float* w1     = (const float*)d_in[7];
    const float* b1     = (const float*)d_in[8];
    const float* w2     = (const float*)d_in[9];
    const float* b2     = (const float*)d_in[10];
    float* out = (float*)d_out;

    cudaFuncSetAttribute(conv_mma<0>, cudaFuncAttributeMaxDynamicSharedMemorySize, DSMEM_BYTES);
    cudaFuncSetAttribute(conv_mma<1>, cudaFuncAttributeMaxDynamicSharedMemorySize, DSMEM_BYTES);
    cudaFuncSetAttribute(conv_mma<0>, cudaFuncAttributePreferredSharedMemoryCarveout,
                         cudaSharedmemCarveoutMaxShared);
    cudaFuncSetAttribute(conv_mma<1>, cudaFuncAttributePreferredSharedMemoryCarveout,
                         cudaSharedmemCarveoutMaxShared);

    offset_mask_conv<<<dim3(8, 8, B * G), 256>>>(o, pw, pb, mw, mb);
    prep_data<<<(B * G * PIX + 255) / 256, 256>>>(anchor, w1, w2);
    deform_kernel<<<dim3(PIX / 256, B * G), 256>>>(cw);

    conv_mma<0><<<dim3(H, B), 256, DSMEM_BYTES>>>(b1, nullptr);
    conv_mma<1><<<dim3(H, B), 256, DSMEM_BYTES>>>(b2, out);
}